// round 3
// baseline (speedup 1.0000x reference)
#include <cuda_runtime.h>
#include <math.h>

#define BATCH 2
#define SEQ   2048
#define HDIM  256
#define NHEAD 8
#define HD    32
#define WIN   32
#define WLEN  65

// ---------------- scratch (static __device__, no allocation) ----------------
// layout (floats):
#define OFF_Q     0
#define OFF_K     1048576
#define OFF_V     2097152
#define OFF_VP    3145728      // vec_proj 12288x512
#define OFF_VD    9437184      // vec_dot 4096x256
#define OFF_VN    10485760     // vec_norm 4096x256
#define OFF_INV   11534336     // invariants 4096x512
#define OFF_XOUT  13631488     // 4096x256
#define OFF_VAGG  14680064     // 4096x3x256
#define OFF_O     17825792     // 4096x768
#define OFF_GATE  20971520     // 4096x256
#define SCRATCH_FLOATS 22020096

__device__ float g_scratch[SCRATCH_FLOATS];

// ---------------- generic tiled fp32 GEMM: C = act(A*B + bias) ----------------
// A logical: M x K (contiguous in K). amode: 0 -> row*lda, 1 -> x_scalar row
// (row*1024), 2 -> vec rows ((4*(row/3)+1+row%3)*256). B: K x Nout row-major.
#define BM 64
#define BN 64
#define BK 16

__global__ __launch_bounds__(256)
void sgemm_kernel(const float* __restrict__ A, const float* __restrict__ Bm,
                  const float* __restrict__ bias, float* __restrict__ C,
                  int M, int Nout, int K, int lda, int amode, int act)
{
    __shared__ __align__(16) float As[BK][68];
    __shared__ __align__(16) float Bs[BK][BN];

    const int tid = threadIdx.x;
    const int tx = tid & 15;       // N micro (x4)
    const int ty = tid >> 4;       // M micro (x4)
    const int m0 = blockIdx.y * BM;
    const int n0 = blockIdx.x * BN;

    // A load mapping: one float4 per thread per k-chunk
    const int mA = tid >> 2;       // 0..63
    const int kq = tid & 3;        // 0..3 (16 floats/row = 4 float4)
    const int rowA = m0 + mA;
    int aoff;
    if (amode == 1)      aoff = rowA * 1024;
    else if (amode == 2) { int t = rowA / 3; int c = rowA - 3 * t; aoff = (4 * t + 1 + c) * 256; }
    else                 aoff = rowA * lda;

    float acc[4][4];
#pragma unroll
    for (int i = 0; i < 4; ++i)
#pragma unroll
        for (int j = 0; j < 4; ++j) acc[i][j] = 0.f;

    for (int k0 = 0; k0 < K; k0 += BK) {
        // load A tile (transposed into As[k][m])
        float4 av = *(const float4*)(A + aoff + k0 + kq * 4);
        As[kq * 4 + 0][mA] = av.x;
        As[kq * 4 + 1][mA] = av.y;
        As[kq * 4 + 2][mA] = av.z;
        As[kq * 4 + 3][mA] = av.w;
        // load B tile
#pragma unroll
        for (int i = 0; i < 4; ++i) {
            int idx = tid + i * 256;
            int kB = idx >> 6, nB = idx & 63;
            Bs[kB][nB] = Bm[(k0 + kB) * Nout + n0 + nB];
        }
        __syncthreads();
#pragma unroll
        for (int kk = 0; kk < BK; ++kk) {
            float4 a4 = *(const float4*)&As[kk][ty * 4];
            float4 b4 = *(const float4*)&Bs[kk][tx * 4];
            float a[4] = {a4.x, a4.y, a4.z, a4.w};
            float b[4] = {b4.x, b4.y, b4.z, b4.w};
#pragma unroll
            for (int i = 0; i < 4; ++i)
#pragma unroll
                for (int j = 0; j < 4; ++j)
                    acc[i][j] = fmaf(a[i], b[j], acc[i][j]);
        }
        __syncthreads();
    }

    float4 bb = make_float4(0.f, 0.f, 0.f, 0.f);
    if (bias) bb = *(const float4*)&bias[n0 + tx * 4];
#pragma unroll
    for (int i = 0; i < 4; ++i) {
        float4 r;
        r.x = acc[i][0] + bb.x;
        r.y = acc[i][1] + bb.y;
        r.z = acc[i][2] + bb.z;
        r.w = acc[i][3] + bb.w;
        if (act == 1) {
            r.x = 1.f / (1.f + __expf(-r.x));
            r.y = 1.f / (1.f + __expf(-r.y));
            r.z = 1.f / (1.f + __expf(-r.z));
            r.w = 1.f / (1.f + __expf(-r.w));
        }
        *(float4*)&C[(m0 + ty * 4 + i) * Nout + n0 + tx * 4] = r;
    }
}

// ---------------- windowed attention: warp per query ----------------
__global__ __launch_bounds__(256)
void attn_kernel(const float* __restrict__ q, const float* __restrict__ k,
                 const float* __restrict__ v, const float* __restrict__ x,
                 float* __restrict__ aw, float* __restrict__ xout,
                 float* __restrict__ vagg)
{
    const float scale = 0.17677669529663687f; // 1/sqrt(32)
    const int lane  = threadIdx.x & 31;
    const int wslot = threadIdx.x >> 5;
    const int gw = blockIdx.x * 8 + wslot;     // global warp = query index
    const int bh = gw >> 11;                   // / SEQ
    const int i  = gw & 2047;
    const int b  = bh >> 3;
    const int hh = bh & 7;
    const int col = hh * HD + lane;

    __shared__ float psh[8][72];

    const float qv = q[(b * SEQ + i) * HDIM + col];

    float s0 = -1e30f, s1 = -1e30f, s2 = -1e30f;
    for (int w = 0; w < WLEN; ++w) {
        int row = i + w - WIN;
        float kv = ((unsigned)row < SEQ) ? k[(b * SEQ + row) * HDIM + col] : 0.f;
        float s = qv * kv;
        s += __shfl_xor_sync(0xffffffffu, s, 16);
        s += __shfl_xor_sync(0xffffffffu, s, 8);
        s += __shfl_xor_sync(0xffffffffu, s, 4);
        s += __shfl_xor_sync(0xffffffffu, s, 2);
        s += __shfl_xor_sync(0xffffffffu, s, 1);
        s *= scale;
        if ((w & 31) == lane) {
            if (w < 32) s0 = s; else if (w < 64) s1 = s; else s2 = s;
        }
    }
    // softmax over 65 scores (zero scores from padding INCLUDED, as in reference)
    float m = fmaxf(s0, s1);
    if (lane == 0) m = fmaxf(m, s2);
#pragma unroll
    for (int o = 16; o; o >>= 1) m = fmaxf(m, __shfl_xor_sync(0xffffffffu, m, o));
    float e0 = __expf(s0 - m);
    float e1 = __expf(s1 - m);
    float e2 = (lane == 0) ? __expf(s2 - m) : 0.f;
    float z = e0 + e1 + e2;
#pragma unroll
    for (int o = 16; o; o >>= 1) z += __shfl_xor_sync(0xffffffffu, z, o);
    float rz = 1.0f / z;
    float p0 = e0 * rz, p1 = e1 * rz, p2 = e2 * rz;

    int awo = (bh * SEQ + i) * WLEN;
    aw[awo + lane] = p0;
    aw[awo + 32 + lane] = p1;
    if (lane == 0) aw[awo + 64] = p2;

    psh[wslot][lane] = p0;
    psh[wslot][32 + lane] = p1;
    if (lane == 0) psh[wslot][64] = p2;
    __syncwarp();

    float ax = 0.f, a0 = 0.f, a1 = 0.f, a2 = 0.f;
    for (int w = 0; w < WLEN; ++w) {
        int row = i + w - WIN;
        if ((unsigned)row >= SEQ) continue;
        float pw = psh[wslot][w];
        ax = fmaf(pw, v[(b * SEQ + row) * HDIM + col], ax);
        const float* xr = x + ((b * SEQ + row) * 4 + 1) * HDIM + col;
        a0 = fmaf(pw, xr[0], a0);
        a1 = fmaf(pw, xr[HDIM], a1);
        a2 = fmaf(pw, xr[2 * HDIM], a2);
    }
    int xo = (b * SEQ + i) * HDIM + col;
    xout[xo] = ax;
    int vo = (b * SEQ + i) * 3 * HDIM + col;
    vagg[vo] = a0;
    vagg[vo + HDIM] = a1;
    vagg[vo + 2 * HDIM] = a2;
}

// ---------------- vec_dot + vec_norm ----------------
__global__ __launch_bounds__(256)
void reduce_kernel(const float* __restrict__ vp, const float* __restrict__ x,
                   float* __restrict__ vd, float* __restrict__ vn)
{
    int idx = blockIdx.x * 256 + threadIdx.x;   // 4096*256
    int bn = idx >> 8, j = idx & 255;
    const float* r = vp + bn * 1536;            // 3 rows of 512
    float dot = r[j] * r[256 + j] + r[512 + j] * r[768 + j] + r[1024 + j] * r[1280 + j];
    const float* xr = x + (bn * 4 + 1) * 256 + j;
    float v0 = xr[0], v1 = xr[256], v2 = xr[512];
    vd[idx] = dot;
    vn[idx] = sqrtf(v0 * v0 + v1 * v1 + v2 * v2);
}

// ---------------- invariants = [ad*vec_dot, an*vec_norm] ----------------
__global__ __launch_bounds__(256)
void invprep_kernel(const float* __restrict__ vd, const float* __restrict__ vn,
                    const float* __restrict__ ad, const float* __restrict__ an,
                    float* __restrict__ inv)
{
    int idx = blockIdx.x * 256 + threadIdx.x;   // 4096*512
    int bn = idx >> 9, kk = idx & 511;
    inv[idx] = (kk < 256) ? ad[0] * vd[bn * 256 + kk]
                          : an[0] * vn[bn * 256 + kk - 256];
}

// ---------------- final epilogue: x_updated + vec_combined ----------------
__global__ __launch_bounds__(256)
void final_kernel(const float* __restrict__ vd, const float* __restrict__ vn,
                  const float* __restrict__ o, const float* __restrict__ gate,
                  const float* __restrict__ vagg, const float* __restrict__ x,
                  float* __restrict__ out)
{
    int idx = blockIdx.x * 256 + threadIdx.x;   // 4096*256
    int bn = idx >> 8, j = idx & 255;
    const float* orow = o + bn * 768;
    float vdv = vd[idx], vnv = vn[idx];
    out[(bn * 4) * 256 + j] = vdv * orow[j] + vnv * orow[256 + j] + orow[512 + j];
    float g = gate[idx];
#pragma unroll
    for (int c = 0; c < 3; ++c) {
        int xoff = (bn * 4 + 1 + c) * 256 + j;
        out[xoff] = g * vagg[(bn * 3 + c) * 256 + j] + x[xoff];
    }
}

// ---------------- launch ----------------
extern "C" void kernel_launch(void* const* d_in, const int* in_sizes, int n_in,
                              void* d_out, int out_size)
{
    const float* x    = (const float*)d_in[0];
    const float* Wq   = (const float*)d_in[1];
    const float* bq   = (const float*)d_in[2];
    const float* Wk   = (const float*)d_in[3];
    const float* bk   = (const float*)d_in[4];
    const float* Wv   = (const float*)d_in[5];
    const float* bv   = (const float*)d_in[6];
    const float* Wo   = (const float*)d_in[7];
    const float* bo   = (const float*)d_in[8];
    const float* Wvec = (const float*)d_in[9];
    const float* ad   = (const float*)d_in[10];
    const float* an   = (const float*)d_in[11];
    const float* Wg   = (const float*)d_in[12];
    const float* bg   = (const float*)d_in[13];

    float* S;
    cudaGetSymbolAddress((void**)&S, g_scratch);
    float* out = (float*)d_out;
    float* aw  = out + BATCH * SEQ * 4 * HDIM;   // x_final first, then attn_weights

    const int M = BATCH * SEQ;   // 4096

    // q,k,v = x_scalar @ W + b
    sgemm_kernel<<<dim3(256 / BN, M / BM), 256>>>(x, Wq, bq, S + OFF_Q, M, 256, 256, 0, 1, 0);
    sgemm_kernel<<<dim3(256 / BN, M / BM), 256>>>(x, Wk, bk, S + OFF_K, M, 256, 256, 0, 1, 0);
    sgemm_kernel<<<dim3(256 / BN, M / BM), 256>>>(x, Wv, bv, S + OFF_V, M, 256, 256, 0, 1, 0);
    // vec_proj = vec @ Wvec   (12288 x 512)
    sgemm_kernel<<<dim3(512 / BN, (3 * M) / BM), 256>>>(x, Wvec, nullptr, S + OFF_VP, 3 * M, 512, 256, 0, 2, 0);
    // vec_dot, vec_norm
    reduce_kernel<<<(M * 256) / 256, 256>>>(S + OFF_VP, x, S + OFF_VD, S + OFF_VN);
    // windowed attention (writes attn_weights, x_out, vec_aggr)
    attn_kernel<<<(16 * SEQ) / 8, 256>>>(S + OFF_Q, S + OFF_K, S + OFF_V, x, aw,
                                         S + OFF_XOUT, S + OFF_VAGG);
    // o = x_out @ Wo + bo
    sgemm_kernel<<<dim3(768 / BN, M / BM), 256>>>(S + OFF_XOUT, Wo, bo, S + OFF_O, M, 768, 256, 256, 0, 0);
    // invariants, gate = sigmoid(inv @ Wg + bg)
    invprep_kernel<<<(M * 512) / 256, 256>>>(S + OFF_VD, S + OFF_VN, ad, an, S + OFF_INV);
    sgemm_kernel<<<dim3(256 / BN, M / BM), 256>>>(S + OFF_INV, Wg, bg, S + OFF_GATE, M, 256, 512, 512, 0, 1);
    // final outputs
    final_kernel<<<(M * 256) / 256, 256>>>(S + OFF_VD, S + OFF_VN, S + OFF_O, S + OFF_GATE,
                                           S + OFF_VAGG, x, out);
}

// round 6
// speedup vs baseline: 2.2696x; 2.2696x over previous
#include <cuda_runtime.h>
#include <math.h>

#define BATCH 2
#define SEQ   2048
#define HDIM  256
#define NHEAD 8
#define HD    32
#define WIN   32
#define WLEN  65

// ---------------- scratch (static __device__, no allocation) ----------------
#define OFF_Q     0
#define OFF_K     1048576
#define OFF_V     2097152
#define OFF_VP    3145728      // vec_proj 12288x512
#define OFF_VD    9437184      // vec_dot 4096x256
#define OFF_VN    10485760     // vec_norm 4096x256
#define OFF_INV   11534336     // invariants 4096x512
#define OFF_XOUT  13631488     // 4096x256
#define OFF_VAGG  14680064     // 4096x3x256
#define OFF_O     17825792     // 4096x768
#define OFF_GATE  20971520     // 4096x256
#define SCRATCH_FLOATS 22020096

__device__ float g_scratch[SCRATCH_FLOATS];

// round-to-nearest fp32 -> tf32 (keeps value in fp32 register, low bits zeroed)
__device__ __forceinline__ float tf32r(float x) {
    unsigned u;
    asm("cvt.rna.tf32.f32 %0, %1;" : "=r"(u) : "f"(x));
    return __uint_as_float(u);
}

// ---------------- TF32 tensor-core GEMM: C = act(A*B + bias) ----------------
// Block tile 128x64, K-step 32, 8 warps; warp tile 32x32 via 8x m16n8k8 mma.
// amode: 0 -> A row stride K, 1 -> x_scalar rows (row*1024),
//        2 -> vec rows ((4*(row/3)+1+row%3)*256)
__global__ __launch_bounds__(256)
void mma_gemm(const float* __restrict__ A, const float* __restrict__ Bm,
              const float* __restrict__ bias, float* __restrict__ C,
              int M, int Nout, int K, int amode, int act)
{
    __shared__ float As[32][136];   // [k][m], stride 136 -> conflict-free frag LDS
    __shared__ float Bs[32][72];    // [k][n], stride 72

    const int tid  = threadIdx.x;
    const int lane = tid & 31;
    const int warp = tid >> 5;
    const int g    = lane >> 2;     // groupID 0..7
    const int tig  = lane & 3;      // threadID_in_group
    const int wm   = (warp & 3) * 32;
    const int wn   = (warp >> 2) * 32;
    const int m0   = blockIdx.y * 128;
    const int n0   = blockIdx.x * 64;

    // global A load mapping: 2 threads per row, 16 floats each
    const int rA = tid >> 1;
    const int kc = (tid & 1) * 16;
    const int rowA = m0 + rA;
    int aoff;
    if (amode == 1)      aoff = rowA * 1024;
    else if (amode == 2) { int t = rowA / 3; int c = rowA - 3 * t; aoff = (4 * t + 1 + c) * 256; }
    else                 aoff = rowA * K;

    // global B load mapping: 32x64 tile, 8 floats per thread
    const int kB = tid >> 3;
    const int nB = (tid & 7) * 8;

    float4 pa[4];
    float4 pb[2];
    {   // prefetch tile 0
        const float* ap = A + aoff + kc;
#pragma unroll
        for (int j = 0; j < 4; ++j) pa[j] = *(const float4*)(ap + j * 4);
        const float* bp = Bm + kB * Nout + n0 + nB;
        pb[0] = *(const float4*)bp;
        pb[1] = *(const float4*)(bp + 4);
    }

    float acc[2][4][4];
#pragma unroll
    for (int mt = 0; mt < 2; ++mt)
#pragma unroll
        for (int nt = 0; nt < 4; ++nt)
#pragma unroll
            for (int r = 0; r < 4; ++r) acc[mt][nt][r] = 0.f;

    for (int k0 = 0; k0 < K; k0 += 32) {
        // store prefetched tile into smem with tf32 rounding
#pragma unroll
        for (int j = 0; j < 4; ++j) {
            As[kc + j * 4 + 0][rA] = tf32r(pa[j].x);
            As[kc + j * 4 + 1][rA] = tf32r(pa[j].y);
            As[kc + j * 4 + 2][rA] = tf32r(pa[j].z);
            As[kc + j * 4 + 3][rA] = tf32r(pa[j].w);
        }
        Bs[kB][nB + 0] = tf32r(pb[0].x);
        Bs[kB][nB + 1] = tf32r(pb[0].y);
        Bs[kB][nB + 2] = tf32r(pb[0].z);
        Bs[kB][nB + 3] = tf32r(pb[0].w);
        Bs[kB][nB + 4] = tf32r(pb[1].x);
        Bs[kB][nB + 5] = tf32r(pb[1].y);
        Bs[kB][nB + 6] = tf32r(pb[1].z);
        Bs[kB][nB + 7] = tf32r(pb[1].w);
        __syncthreads();

        const int k1 = k0 + 32;
        if (k1 < K) {   // prefetch next tile (overlaps the MMA section)
            const float* ap = A + aoff + k1 + kc;
#pragma unroll
            for (int j = 0; j < 4; ++j) pa[j] = *(const float4*)(ap + j * 4);
            const float* bp = Bm + (k1 + kB) * Nout + n0 + nB;
            pb[0] = *(const float4*)bp;
            pb[1] = *(const float4*)(bp + 4);
        }

#pragma unroll
        for (int kq = 0; kq < 4; ++kq) {
            const int kk = kq * 8;
            unsigned a[2][4], b[4][2];
#pragma unroll
            for (int mt = 0; mt < 2; ++mt) {
                const int mr = wm + mt * 16 + g;
                a[mt][0] = __float_as_uint(As[kk + tig][mr]);
                a[mt][1] = __float_as_uint(As[kk + tig][mr + 8]);
                a[mt][2] = __float_as_uint(As[kk + tig + 4][mr]);
                a[mt][3] = __float_as_uint(As[kk + tig + 4][mr + 8]);
            }
#pragma unroll
            for (int nt = 0; nt < 4; ++nt) {
                const int nc = wn + nt * 8 + g;
                b[nt][0] = __float_as_uint(Bs[kk + tig][nc]);
                b[nt][1] = __float_as_uint(Bs[kk + tig + 4][nc]);
            }
#pragma unroll
            for (int mt = 0; mt < 2; ++mt)
#pragma unroll
                for (int nt = 0; nt < 4; ++nt)
                    asm volatile(
                        "mma.sync.aligned.m16n8k8.row.col.f32.tf32.tf32.f32 "
                        "{%0,%1,%2,%3}, {%4,%5,%6,%7}, {%8,%9}, {%0,%1,%2,%3};"
                        : "+f"(acc[mt][nt][0]), "+f"(acc[mt][nt][1]),
                          "+f"(acc[mt][nt][2]), "+f"(acc[mt][nt][3])
                        : "r"(a[mt][0]), "r"(a[mt][1]), "r"(a[mt][2]), "r"(a[mt][3]),
                          "r"(b[nt][0]), "r"(b[nt][1]));
        }
        __syncthreads();
    }

    // epilogue
#pragma unroll
    for (int mt = 0; mt < 2; ++mt) {
        const int row = m0 + wm + mt * 16 + g;
#pragma unroll
        for (int nt = 0; nt < 4; ++nt) {
            const int col = n0 + wn + nt * 8 + 2 * tig;
            float b0 = 0.f, b1 = 0.f;
            if (bias) { b0 = bias[col]; b1 = bias[col + 1]; }
            float2 r0 = make_float2(acc[mt][nt][0] + b0, acc[mt][nt][1] + b1);
            float2 r1 = make_float2(acc[mt][nt][2] + b0, acc[mt][nt][3] + b1);
            if (act == 1) {
                r0.x = 1.f / (1.f + __expf(-r0.x));
                r0.y = 1.f / (1.f + __expf(-r0.y));
                r1.x = 1.f / (1.f + __expf(-r1.x));
                r1.y = 1.f / (1.f + __expf(-r1.y));
            }
            *(float2*)&C[row * Nout + col] = r0;
            *(float2*)&C[(row + 8) * Nout + col] = r1;
        }
    }
}

// ---------------- windowed attention: warp per query ----------------
__global__ __launch_bounds__(256)
void attn_kernel(const float* __restrict__ q, const float* __restrict__ k,
                 const float* __restrict__ v, const float* __restrict__ x,
                 float* __restrict__ aw, float* __restrict__ xout,
                 float* __restrict__ vagg)
{
    const float scale = 0.17677669529663687f; // 1/sqrt(32)
    const int lane  = threadIdx.x & 31;
    const int wslot = threadIdx.x >> 5;
    const int gw = blockIdx.x * 8 + wslot;     // global warp = query index
    const int bh = gw >> 11;                   // / SEQ
    const int i  = gw & 2047;
    const int b  = bh >> 3;
    const int hh = bh & 7;
    const int col = hh * HD + lane;

    __shared__ float psh[8][72];

    const float qv = q[(b * SEQ + i) * HDIM + col];

    float s0 = -1e30f, s1 = -1e30f, s2 = -1e30f;
    for (int w = 0; w < WLEN; ++w) {
        int row = i + w - WIN;
        float kv = ((unsigned)row < SEQ) ? k[(b * SEQ + row) * HDIM + col] : 0.f;
        float s = qv * kv;
        s += __shfl_xor_sync(0xffffffffu, s, 16);
        s += __shfl_xor_sync(0xffffffffu, s, 8);
        s += __shfl_xor_sync(0xffffffffu, s, 4);
        s += __shfl_xor_sync(0xffffffffu, s, 2);
        s += __shfl_xor_sync(0xffffffffu, s, 1);
        s *= scale;
        if ((w & 31) == lane) {
            if (w < 32) s0 = s; else if (w < 64) s1 = s; else s2 = s;
        }
    }
    // softmax over 65 scores (zero scores from padding INCLUDED, as in reference)
    float m = fmaxf(s0, s1);
    if (lane == 0) m = fmaxf(m, s2);
#pragma unroll
    for (int o = 16; o; o >>= 1) m = fmaxf(m, __shfl_xor_sync(0xffffffffu, m, o));
    float e0 = __expf(s0 - m);
    float e1 = __expf(s1 - m);
    float e2 = (lane == 0) ? __expf(s2 - m) : 0.f;
    float z = e0 + e1 + e2;
#pragma unroll
    for (int o = 16; o; o >>= 1) z += __shfl_xor_sync(0xffffffffu, z, o);
    float rz = 1.0f / z;
    float p0 = e0 * rz, p1 = e1 * rz, p2 = e2 * rz;

    int awo = (bh * SEQ + i) * WLEN;
    aw[awo + lane] = p0;
    aw[awo + 32 + lane] = p1;
    if (lane == 0) aw[awo + 64] = p2;

    psh[wslot][lane] = p0;
    psh[wslot][32 + lane] = p1;
    if (lane == 0) psh[wslot][64] = p2;
    __syncwarp();

    float ax = 0.f, a0 = 0.f, a1 = 0.f, a2 = 0.f;
    for (int w = 0; w < WLEN; ++w) {
        int row = i + w - WIN;
        if ((unsigned)row >= SEQ) continue;
        float pw = psh[wslot][w];
        ax = fmaf(pw, v[(b * SEQ + row) * HDIM + col], ax);
        const float* xr = x + ((b * SEQ + row) * 4 + 1) * HDIM + col;
        a0 = fmaf(pw, xr[0], a0);
        a1 = fmaf(pw, xr[HDIM], a1);
        a2 = fmaf(pw, xr[2 * HDIM], a2);
    }
    int xo = (b * SEQ + i) * HDIM + col;
    xout[xo] = ax;
    int vo = (b * SEQ + i) * 3 * HDIM + col;
    vagg[vo] = a0;
    vagg[vo + HDIM] = a1;
    vagg[vo + 2 * HDIM] = a2;
}

// ---------------- vec_dot + vec_norm ----------------
__global__ __launch_bounds__(256)
void reduce_kernel(const float* __restrict__ vp, const float* __restrict__ x,
                   float* __restrict__ vd, float* __restrict__ vn)
{
    int idx = blockIdx.x * 256 + threadIdx.x;   // 4096*256
    int bn = idx >> 8, j = idx & 255;
    const float* r = vp + bn * 1536;            // 3 rows of 512
    float dot = r[j] * r[256 + j] + r[512 + j] * r[768 + j] + r[1024 + j] * r[1280 + j];
    const float* xr = x + (bn * 4 + 1) * 256 + j;
    float v0 = xr[0], v1 = xr[256], v2 = xr[512];
    vd[idx] = dot;
    vn[idx] = sqrtf(v0 * v0 + v1 * v1 + v2 * v2);
}

// ---------------- invariants = [ad*vec_dot, an*vec_norm] ----------------
__global__ __launch_bounds__(256)
void invprep_kernel(const float* __restrict__ vd, const float* __restrict__ vn,
                    const float* __restrict__ ad, const float* __restrict__ an,
                    float* __restrict__ inv)
{
    int idx = blockIdx.x * 256 + threadIdx.x;   // 4096*512
    int bn = idx >> 9, kk = idx & 511;
    inv[idx] = (kk < 256) ? ad[0] * vd[bn * 256 + kk]
                          : an[0] * vn[bn * 256 + kk - 256];
}

// ---------------- final epilogue ----------------
__global__ __launch_bounds__(256)
void final_kernel(const float* __restrict__ vd, const float* __restrict__ vn,
                  const float* __restrict__ o, const float* __restrict__ gate,
                  const float* __restrict__ vagg, const float* __restrict__ x,
                  float* __restrict__ out)
{
    int idx = blockIdx.x * 256 + threadIdx.x;   // 4096*256
    int bn = idx >> 8, j = idx & 255;
    const float* orow = o + bn * 768;
    float vdv = vd[idx], vnv = vn[idx];
    out[(bn * 4) * 256 + j] = vdv * orow[j] + vnv * orow[256 + j] + orow[512 + j];
    float g = gate[idx];
#pragma unroll
    for (int c = 0; c < 3; ++c) {
        int xoff = (bn * 4 + 1 + c) * 256 + j;
        out[xoff] = g * vagg[(bn * 3 + c) * 256 + j] + x[xoff];
    }
}

// ---------------- launch ----------------
extern "C" void kernel_launch(void* const* d_in, const int* in_sizes, int n_in,
                              void* d_out, int out_size)
{
    const float* x    = (const float*)d_in[0];
    const float* Wq   = (const float*)d_in[1];
    const float* bq   = (const float*)d_in[2];
    const float* Wk   = (const float*)d_in[3];
    const float* bk   = (const float*)d_in[4];
    const float* Wv   = (const float*)d_in[5];
    const float* bv   = (const float*)d_in[6];
    const float* Wo   = (const float*)d_in[7];
    const float* bo   = (const float*)d_in[8];
    const float* Wvec = (const float*)d_in[9];
    const float* ad   = (const float*)d_in[10];
    const float* an   = (const float*)d_in[11];
    const float* Wg   = (const float*)d_in[12];
    const float* bg   = (const float*)d_in[13];

    float* S;
    cudaGetSymbolAddress((void**)&S, g_scratch);
    float* out = (float*)d_out;
    float* aw  = out + BATCH * SEQ * 4 * HDIM;   // x_final first, then attn_weights

    const int M = BATCH * SEQ;   // 4096

    // q,k,v = x_scalar @ W + b   (TF32 tensor cores)
    mma_gemm<<<dim3(256 / 64, M / 128), 256>>>(x, Wq, bq, S + OFF_Q, M, 256, 256, 1, 0);
    mma_gemm<<<dim3(256 / 64, M / 128), 256>>>(x, Wk, bk, S + OFF_K, M, 256, 256, 1, 0);
    mma_gemm<<<dim3(256 / 64, M / 128), 256>>>(x, Wv, bv, S + OFF_V, M, 256, 256, 1, 0);
    // vec_proj = vec @ Wvec   (12288 x 512)
    mma_gemm<<<dim3(512 / 64, (3 * M) / 128), 256>>>(x, Wvec, nullptr, S + OFF_VP, 3 * M, 512, 256, 2, 0);
    // vec_dot, vec_norm
    reduce_kernel<<<(M * 256) / 256, 256>>>(S + OFF_VP, x, S + OFF_VD, S + OFF_VN);
    // windowed attention (writes attn_weights, x_out, vec_aggr)
    attn_kernel<<<(16 * SEQ) / 8, 256>>>(S + OFF_Q, S + OFF_K, S + OFF_V, x, aw,
                                         S + OFF_XOUT, S + OFF_VAGG);
    // o = x_out @ Wo + bo
    mma_gemm<<<dim3(768 / 64, M / 128), 256>>>(S + OFF_XOUT, Wo, bo, S + OFF_O, M, 768, 256, 0, 0);
    // invariants, gate = sigmoid(inv @ Wg + bg)
    invprep_kernel<<<(M * 512) / 256, 256>>>(S + OFF_VD, S + OFF_VN, ad, an, S + OFF_INV);
    mma_gemm<<<dim3(256 / 64, M / 128), 256>>>(S + OFF_INV, Wg, bg, S + OFF_GATE, M, 256, 512, 0, 1);
    // final outputs
    final_kernel<<<(M * 256) / 256, 256>>>(S + OFF_VD, S + OFF_VN, S + OFF_O, S + OFF_GATE,
                                           S + OFF_VAGG, x, out);
}

// round 7
// speedup vs baseline: 2.9424x; 1.2964x over previous
#include <cuda_runtime.h>
#include <math.h>

#define BATCH 2
#define SEQ   2048
#define HDIM  256
#define NHEAD 8
#define HD    32
#define WIN   32
#define WLEN  65

// ---------------- scratch (static __device__, no allocation) ----------------
#define OFF_Q     0
#define OFF_K     1048576
#define OFF_V     2097152
#define OFF_VP    3145728      // vec_proj 12288x512
#define OFF_VD    9437184      // vec_dot 4096x256
#define OFF_VN    10485760     // vec_norm 4096x256
#define OFF_INV   11534336     // invariants 4096x512
#define OFF_XOUT  13631488     // 4096x256
#define OFF_VAGG  14680064     // 4096x3x256
#define OFF_O     17825792     // 4096x768
#define OFF_GATE  20971520     // 4096x256
#define SCRATCH_FLOATS 22020096

__device__ float g_scratch[SCRATCH_FLOATS];

// round-to-nearest fp32 -> tf32
__device__ __forceinline__ float tf32r(float x) {
    unsigned u;
    asm("cvt.rna.tf32.f32 %0, %1;" : "=r"(u) : "f"(x));
    return __uint_as_float(u);
}
__device__ __forceinline__ float4 tf32r4(float4 v) {
    return make_float4(tf32r(v.x), tf32r(v.y), tf32r(v.z), tf32r(v.w));
}

// ---------------- TF32 tensor-core GEMM: C = act(A*B + bias) ----------------
// Block tile 128x64, K-step 32, 8 warps; warp tile 32x32 via 8x m16n8k8 mma.
// A smem [m][36]: STS.128 conflict-free, fragment LDS banks 4g+tig (distinct).
// blockIdx.z selects (B,bias,C-offset) — used to fuse the 3 QKV GEMMs.
// amode: 0 -> A row stride K, 1 -> x_scalar rows (row*1024),
//        2 -> vec rows ((4*(row/3)+1+row%3)*256)
__global__ __launch_bounds__(256)
void mma_gemm(const float* __restrict__ A,
              const float* __restrict__ B0, const float* __restrict__ B1,
              const float* __restrict__ B2,
              const float* __restrict__ c0, const float* __restrict__ c1,
              const float* __restrict__ c2,
              float* __restrict__ C, int Cstride,
              int M, int Nout, int K, int amode, int act)
{
    __shared__ __align__(16) float As[128][36];
    __shared__ __align__(16) float Bs[32][72];

    const int z = blockIdx.z;
    const float* Bm   = (z == 0) ? B0 : (z == 1) ? B1 : B2;
    const float* bias = (z == 0) ? c0 : (z == 1) ? c1 : c2;
    C += (size_t)z * Cstride;

    const int tid  = threadIdx.x;
    const int lane = tid & 31;
    const int warp = tid >> 5;
    const int g    = lane >> 2;
    const int tig  = lane & 3;
    const int wm   = (warp & 3) * 32;
    const int wn   = (warp >> 2) * 32;
    const int m0   = blockIdx.y * 128;
    const int n0   = blockIdx.x * 64;

    // A global mapping: 2 threads per row, 16 floats each
    const int rA = tid >> 1;
    const int kc = (tid & 1) * 16;
    const int rowA = m0 + rA;
    int aoff;
    if (amode == 1)      aoff = rowA * 1024;
    else if (amode == 2) { int t = rowA / 3; int c = rowA - 3 * t; aoff = (4 * t + 1 + c) * 256; }
    else                 aoff = rowA * K;

    // B global mapping: 32x64 tile, 8 floats per thread
    const int kB = tid >> 3;
    const int nB = (tid & 7) * 8;

    float4 pa[4];
    float4 pb[2];
    {   // prefetch tile 0
        const float* ap = A + aoff + kc;
#pragma unroll
        for (int j = 0; j < 4; ++j) pa[j] = *(const float4*)(ap + j * 4);
        const float* bp = Bm + kB * Nout + n0 + nB;
        pb[0] = *(const float4*)bp;
        pb[1] = *(const float4*)(bp + 4);
    }

    float acc[2][4][4];
#pragma unroll
    for (int mt = 0; mt < 2; ++mt)
#pragma unroll
        for (int nt = 0; nt < 4; ++nt)
#pragma unroll
            for (int r = 0; r < 4; ++r) acc[mt][nt][r] = 0.f;

    for (int k0 = 0; k0 < K; k0 += 32) {
        // vectorized, conflict-free smem stores (tf32-rounded)
#pragma unroll
        for (int j = 0; j < 4; ++j)
            *(float4*)&As[rA][kc + j * 4] = tf32r4(pa[j]);
        *(float4*)&Bs[kB][nB]     = tf32r4(pb[0]);
        *(float4*)&Bs[kB][nB + 4] = tf32r4(pb[1]);
        __syncthreads();

        const int k1 = k0 + 32;
        if (k1 < K) {   // prefetch next tile
            const float* ap = A + aoff + k1 + kc;
#pragma unroll
            for (int j = 0; j < 4; ++j) pa[j] = *(const float4*)(ap + j * 4);
            const float* bp = Bm + (k1 + kB) * Nout + n0 + nB;
            pb[0] = *(const float4*)bp;
            pb[1] = *(const float4*)(bp + 4);
        }

#pragma unroll
        for (int kq = 0; kq < 4; ++kq) {
            const int kk = kq * 8;
            unsigned a[2][4], b[4][2];
#pragma unroll
            for (int mt = 0; mt < 2; ++mt) {
                const int mr = wm + mt * 16 + g;
                a[mt][0] = __float_as_uint(As[mr][kk + tig]);
                a[mt][1] = __float_as_uint(As[mr + 8][kk + tig]);
                a[mt][2] = __float_as_uint(As[mr][kk + tig + 4]);
                a[mt][3] = __float_as_uint(As[mr + 8][kk + tig + 4]);
            }
#pragma unroll
            for (int nt = 0; nt < 4; ++nt) {
                const int nc = wn + nt * 8 + g;
                b[nt][0] = __float_as_uint(Bs[kk + tig][nc]);
                b[nt][1] = __float_as_uint(Bs[kk + tig + 4][nc]);
            }
#pragma unroll
            for (int mt = 0; mt < 2; ++mt)
#pragma unroll
                for (int nt = 0; nt < 4; ++nt)
                    asm volatile(
                        "mma.sync.aligned.m16n8k8.row.col.f32.tf32.tf32.f32 "
                        "{%0,%1,%2,%3}, {%4,%5,%6,%7}, {%8,%9}, {%0,%1,%2,%3};"
                        : "+f"(acc[mt][nt][0]), "+f"(acc[mt][nt][1]),
                          "+f"(acc[mt][nt][2]), "+f"(acc[mt][nt][3])
                        : "r"(a[mt][0]), "r"(a[mt][1]), "r"(a[mt][2]), "r"(a[mt][3]),
                          "r"(b[nt][0]), "r"(b[nt][1]));
        }
        __syncthreads();
    }

    // epilogue
#pragma unroll
    for (int mt = 0; mt < 2; ++mt) {
        const int row = m0 + wm + mt * 16 + g;
#pragma unroll
        for (int nt = 0; nt < 4; ++nt) {
            const int col = n0 + wn + nt * 8 + 2 * tig;
            float b0 = 0.f, b1 = 0.f;
            if (bias) { b0 = bias[col]; b1 = bias[col + 1]; }
            float2 r0 = make_float2(acc[mt][nt][0] + b0, acc[mt][nt][1] + b1);
            float2 r1 = make_float2(acc[mt][nt][2] + b0, acc[mt][nt][3] + b1);
            if (act == 1) {
                r0.x = 1.f / (1.f + __expf(-r0.x));
                r0.y = 1.f / (1.f + __expf(-r0.y));
                r1.x = 1.f / (1.f + __expf(-r1.x));
                r1.y = 1.f / (1.f + __expf(-r1.y));
            }
            *(float2*)&C[row * Nout + col] = r0;
            *(float2*)&C[(row + 8) * Nout + col] = r1;
        }
    }
}

// ---------------- windowed attention, smem-staged K ----------------
// Block: 8 warps = 8 consecutive queries of one (b,h). K window tile staged in
// smem (zero-padded, so padded scores are exactly 0 like the reference).
// Score phase: each lane computes full dot products for w=lane, lane+32, 64.
// Aggregation: lane = (plane p, d/4); one LDG.128 per window position.
__global__ __launch_bounds__(256)
void attn_kernel(const float* __restrict__ q, const float* __restrict__ k,
                 const float* __restrict__ v, const float* __restrict__ x,
                 float* __restrict__ aw, float* __restrict__ xout,
                 float* __restrict__ vagg)
{
    const float scale = 0.17677669529663687f; // 1/sqrt(32)
    __shared__ float Ksh[72][33];
    __shared__ float Qsh[8][32];
    __shared__ float Psh[8][72];

    const int tid  = threadIdx.x;
    const int lane = tid & 31;
    const int wq   = tid >> 5;
    const int i0   = blockIdx.x * 8;
    const int bh   = blockIdx.y;
    const int b    = bh >> 3;
    const int hh   = bh & 7;
    const int colb = hh * HD;

    // stage K window rows [i0-32, i0+39], zero for OOB
    for (int e = tid; e < 72 * 32; e += 256) {
        int r = e >> 5, d = e & 31;
        int seq = i0 + r - WIN;
        Ksh[r][d] = ((unsigned)seq < SEQ) ? k[(b * SEQ + seq) * HDIM + colb + d] : 0.f;
    }
    {   // stage Q for the 8 queries
        int q8 = tid >> 5, d = tid & 31;
        Qsh[q8][d] = q[(b * SEQ + i0 + q8) * HDIM + colb + d];
    }
    __syncthreads();

    const int i = i0 + wq;

    // scores: lane handles w = lane, lane+32; all lanes compute w=64 (broadcast)
    float s0 = 0.f, s1 = 0.f, s2 = 0.f;
    {
        const float* kr0 = &Ksh[lane + wq][0];
        const float* kr1 = &Ksh[lane + 32 + wq][0];
        const float* kr2 = &Ksh[64 + wq][0];
        const float* qr  = &Qsh[wq][0];
#pragma unroll
        for (int d = 0; d < 32; ++d) {
            float qd = qr[d];
            s0 = fmaf(qd, kr0[d], s0);
            s1 = fmaf(qd, kr1[d], s1);
            s2 = fmaf(qd, kr2[d], s2);
        }
    }
    s0 *= scale; s1 *= scale; s2 *= scale;

    // softmax over 65 scores (padded zero-scores included, matching reference)
    float m = fmaxf(fmaxf(s0, s1), s2);
#pragma unroll
    for (int o = 16; o; o >>= 1) m = fmaxf(m, __shfl_xor_sync(0xffffffffu, m, o));
    float e0 = __expf(s0 - m);
    float e1 = __expf(s1 - m);
    float e2 = __expf(s2 - m);
    float zz = e0 + e1 + ((lane == 0) ? e2 : 0.f);
#pragma unroll
    for (int o = 16; o; o >>= 1) zz += __shfl_xor_sync(0xffffffffu, zz, o);
    float rz = 1.0f / zz;
    float p0 = e0 * rz, p1 = e1 * rz, p2 = e2 * rz;

    int awo = (bh * SEQ + i) * WLEN;
    aw[awo + lane] = p0;
    aw[awo + 32 + lane] = p1;
    if (lane == 0) aw[awo + 64] = p2;

    Psh[wq][lane] = p0;
    Psh[wq][32 + lane] = p1;
    if (lane == 0) Psh[wq][64] = p2;
    __syncwarp();

    // aggregation: lane = (plane p in 0..3, 4 dims)
    const int p  = lane >> 3;
    const int d4 = (lane & 7) * 4;
    const float* base;
    int rstride;
    if (p == 0) { base = v + (size_t)(b * SEQ) * HDIM + colb + d4; rstride = HDIM; }
    else        { base = x + ((size_t)(b * SEQ) * 4 + p) * HDIM + colb + d4; rstride = 4 * HDIM; }

    float4 acc = make_float4(0.f, 0.f, 0.f, 0.f);
    const float* prow = &Psh[wq][0];
    for (int w = 0; w < WLEN; ++w) {
        int row = i + w - WIN;
        if ((unsigned)row >= SEQ) continue;
        float pw = prow[w];
        float4 vv = *(const float4*)(base + (size_t)row * rstride);
        acc.x = fmaf(pw, vv.x, acc.x);
        acc.y = fmaf(pw, vv.y, acc.y);
        acc.z = fmaf(pw, vv.z, acc.z);
        acc.w = fmaf(pw, vv.w, acc.w);
    }
    if (p == 0)
        *(float4*)&xout[(size_t)(b * SEQ + i) * HDIM + colb + d4] = acc;
    else
        *(float4*)&vagg[((size_t)(b * SEQ + i) * 3 + (p - 1)) * HDIM + colb + d4] = acc;
}

// ---------------- vec_dot + vec_norm + invariants (fused) ----------------
__global__ __launch_bounds__(256)
void reduce_inv_kernel(const float* __restrict__ vp, const float* __restrict__ x,
                       const float* __restrict__ ad, const float* __restrict__ an,
                       float* __restrict__ vd, float* __restrict__ vn,
                       float* __restrict__ inv)
{
    int idx = blockIdx.x * 256 + threadIdx.x;   // 4096*256
    int bn = idx >> 8, j = idx & 255;
    const float* r = vp + bn * 1536;            // 3 rows of 512
    float dot = r[j] * r[256 + j] + r[512 + j] * r[768 + j] + r[1024 + j] * r[1280 + j];
    const float* xr = x + (bn * 4 + 1) * 256 + j;
    float v0 = xr[0], v1 = xr[256], v2 = xr[512];
    float nrm = sqrtf(v0 * v0 + v1 * v1 + v2 * v2);
    vd[idx] = dot;
    vn[idx] = nrm;
    inv[bn * 512 + j]       = ad[0] * dot;
    inv[bn * 512 + 256 + j] = an[0] * nrm;
}

// ---------------- final epilogue ----------------
__global__ __launch_bounds__(256)
void final_kernel(const float* __restrict__ vd, const float* __restrict__ vn,
                  const float* __restrict__ o, const float* __restrict__ gate,
                  const float* __restrict__ vagg, const float* __restrict__ x,
                  float* __restrict__ out)
{
    int idx = blockIdx.x * 256 + threadIdx.x;   // 4096*256
    int bn = idx >> 8, j = idx & 255;
    const float* orow = o + bn * 768;
    float vdv = vd[idx], vnv = vn[idx];
    out[(bn * 4) * 256 + j] = vdv * orow[j] + vnv * orow[256 + j] + orow[512 + j];
    float g = gate[idx];
#pragma unroll
    for (int c = 0; c < 3; ++c) {
        int xoff = (bn * 4 + 1 + c) * 256 + j;
        out[xoff] = g * vagg[(bn * 3 + c) * 256 + j] + x[xoff];
    }
}

// ---------------- launch ----------------
extern "C" void kernel_launch(void* const* d_in, const int* in_sizes, int n_in,
                              void* d_out, int out_size)
{
    const float* x    = (const float*)d_in[0];
    const float* Wq   = (const float*)d_in[1];
    const float* bq   = (const float*)d_in[2];
    const float* Wk   = (const float*)d_in[3];
    const float* bk   = (const float*)d_in[4];
    const float* Wv   = (const float*)d_in[5];
    const float* bv   = (const float*)d_in[6];
    const float* Wo   = (const float*)d_in[7];
    const float* bo   = (const float*)d_in[8];
    const float* Wvec = (const float*)d_in[9];
    const float* ad   = (const float*)d_in[10];
    const float* an   = (const float*)d_in[11];
    const float* Wg   = (const float*)d_in[12];
    const float* bg   = (const float*)d_in[13];

    float* S;
    cudaGetSymbolAddress((void**)&S, g_scratch);
    float* out = (float*)d_out;
    float* aw  = out + BATCH * SEQ * 4 * HDIM;   // x_final first, then attn_weights

    const int M = BATCH * SEQ;   // 4096

    // q,k,v = x_scalar @ W + b  (fused into one launch via blockIdx.z)
    mma_gemm<<<dim3(4, 32, 3), 256>>>(x, Wq, Wk, Wv, bq, bk, bv,
                                      S + OFF_Q, 1048576, M, 256, 256, 1, 0);
    // vec_proj = vec @ Wvec   (12288 x 512)
    mma_gemm<<<dim3(8, 96, 1), 256>>>(x, Wvec, Wvec, Wvec, nullptr, nullptr, nullptr,
                                      S + OFF_VP, 0, 3 * M, 512, 256, 2, 0);
    // vec_dot, vec_norm, invariants
    reduce_inv_kernel<<<M, 256>>>(S + OFF_VP, x, ad, an,
                                  S + OFF_VD, S + OFF_VN, S + OFF_INV);
    // windowed attention (writes attn_weights, x_out, vec_aggr)
    attn_kernel<<<dim3(SEQ / 8, 16), 256>>>(S + OFF_Q, S + OFF_K, S + OFF_V, x, aw,
                                            S + OFF_XOUT, S + OFF_VAGG);
    // o = x_out @ Wo + bo
    mma_gemm<<<dim3(12, 32, 1), 256>>>(S + OFF_XOUT, Wo, Wo, Wo, bo, bo, bo,
                                       S + OFF_O, 0, M, 768, 256, 0, 0);
    // gate = sigmoid(inv @ Wg + bg)
    mma_gemm<<<dim3(4, 32, 1), 256>>>(S + OFF_INV, Wg, Wg, Wg, bg, bg, bg,
                                      S + OFF_GATE, 0, M, 256, 512, 0, 1);
    // final outputs
    final_kernel<<<M, 256>>>(S + OFF_VD, S + OFF_VN, S + OFF_O, S + OFF_GATE,
                             S + OFF_VAGG, x, out);
}

// round 8
// speedup vs baseline: 3.1843x; 1.0822x over previous
#include <cuda_runtime.h>
#include <math.h>

#define BATCH 2
#define SEQ   2048
#define HDIM  256
#define NHEAD 8
#define HD    32
#define WIN   32
#define WLEN  65

// ---------------- scratch (static __device__, no allocation) ----------------
#define OFF_Q     0
#define OFF_K     1048576
#define OFF_V     2097152
#define OFF_VP    3145728      // vec_proj 12288x512
#define OFF_VD    9437184      // vec_dot 4096x256
#define OFF_VN    10485760     // vec_norm 4096x256
#define OFF_INV   11534336     // invariants 4096x512
#define OFF_XOUT  13631488     // 4096x256
#define OFF_VAGG  14680064     // 4096x3x256
#define OFF_O     17825792     // 4096x768
#define OFF_GATE  20971520     // 4096x256
#define SCRATCH_FLOATS 22020096

__device__ float g_scratch[SCRATCH_FLOATS];

// round-to-nearest fp32 -> tf32
__device__ __forceinline__ float tf32r(float x) {
    unsigned u;
    asm("cvt.rna.tf32.f32 %0, %1;" : "=r"(u) : "f"(x));
    return __uint_as_float(u);
}
__device__ __forceinline__ float4 tf32r4(float4 v) {
    return make_float4(tf32r(v.x), tf32r(v.y), tf32r(v.z), tf32r(v.w));
}

// ---------------- TF32 tensor-core GEMM: C = act(A*B + bias) ----------------
__global__ __launch_bounds__(256)
void mma_gemm(const float* __restrict__ A,
              const float* __restrict__ B0, const float* __restrict__ B1,
              const float* __restrict__ B2,
              const float* __restrict__ c0, const float* __restrict__ c1,
              const float* __restrict__ c2,
              float* __restrict__ C, int Cstride,
              int M, int Nout, int K, int amode, int act)
{
    __shared__ __align__(16) float As[128][36];
    __shared__ __align__(16) float Bs[32][72];

    const int z = blockIdx.z;
    const float* Bm   = (z == 0) ? B0 : (z == 1) ? B1 : B2;
    const float* bias = (z == 0) ? c0 : (z == 1) ? c1 : c2;
    C += (size_t)z * Cstride;

    const int tid  = threadIdx.x;
    const int lane = tid & 31;
    const int warp = tid >> 5;
    const int g    = lane >> 2;
    const int tig  = lane & 3;
    const int wm   = (warp & 3) * 32;
    const int wn   = (warp >> 2) * 32;
    const int m0   = blockIdx.y * 128;
    const int n0   = blockIdx.x * 64;

    const int rA = tid >> 1;
    const int kc = (tid & 1) * 16;
    const int rowA = m0 + rA;
    int aoff;
    if (amode == 1)      aoff = rowA * 1024;
    else if (amode == 2) { int t = rowA / 3; int c = rowA - 3 * t; aoff = (4 * t + 1 + c) * 256; }
    else                 aoff = rowA * K;

    const int kB = tid >> 3;
    const int nB = (tid & 7) * 8;

    float4 pa[4];
    float4 pb[2];
    {
        const float* ap = A + aoff + kc;
#pragma unroll
        for (int j = 0; j < 4; ++j) pa[j] = *(const float4*)(ap + j * 4);
        const float* bp = Bm + kB * Nout + n0 + nB;
        pb[0] = *(const float4*)bp;
        pb[1] = *(const float4*)(bp + 4);
    }

    float acc[2][4][4];
#pragma unroll
    for (int mt = 0; mt < 2; ++mt)
#pragma unroll
        for (int nt = 0; nt < 4; ++nt)
#pragma unroll
            for (int r = 0; r < 4; ++r) acc[mt][nt][r] = 0.f;

    for (int k0 = 0; k0 < K; k0 += 32) {
#pragma unroll
        for (int j = 0; j < 4; ++j)
            *(float4*)&As[rA][kc + j * 4] = tf32r4(pa[j]);
        *(float4*)&Bs[kB][nB]     = tf32r4(pb[0]);
        *(float4*)&Bs[kB][nB + 4] = tf32r4(pb[1]);
        __syncthreads();

        const int k1 = k0 + 32;
        if (k1 < K) {
            const float* ap = A + aoff + k1 + kc;
#pragma unroll
            for (int j = 0; j < 4; ++j) pa[j] = *(const float4*)(ap + j * 4);
            const float* bp = Bm + (k1 + kB) * Nout + n0 + nB;
            pb[0] = *(const float4*)bp;
            pb[1] = *(const float4*)(bp + 4);
        }

#pragma unroll
        for (int kq = 0; kq < 4; ++kq) {
            const int kk = kq * 8;
            unsigned a[2][4], b[4][2];
#pragma unroll
            for (int mt = 0; mt < 2; ++mt) {
                const int mr = wm + mt * 16 + g;
                a[mt][0] = __float_as_uint(As[mr][kk + tig]);
                a[mt][1] = __float_as_uint(As[mr + 8][kk + tig]);
                a[mt][2] = __float_as_uint(As[mr][kk + tig + 4]);
                a[mt][3] = __float_as_uint(As[mr + 8][kk + tig + 4]);
            }
#pragma unroll
            for (int nt = 0; nt < 4; ++nt) {
                const int nc = wn + nt * 8 + g;
                b[nt][0] = __float_as_uint(Bs[kk + tig][nc]);
                b[nt][1] = __float_as_uint(Bs[kk + tig + 4][nc]);
            }
#pragma unroll
            for (int mt = 0; mt < 2; ++mt)
#pragma unroll
                for (int nt = 0; nt < 4; ++nt)
                    asm volatile(
                        "mma.sync.aligned.m16n8k8.row.col.f32.tf32.tf32.f32 "
                        "{%0,%1,%2,%3}, {%4,%5,%6,%7}, {%8,%9}, {%0,%1,%2,%3};"
                        : "+f"(acc[mt][nt][0]), "+f"(acc[mt][nt][1]),
                          "+f"(acc[mt][nt][2]), "+f"(acc[mt][nt][3])
                        : "r"(a[mt][0]), "r"(a[mt][1]), "r"(a[mt][2]), "r"(a[mt][3]),
                          "r"(b[nt][0]), "r"(b[nt][1]));
        }
        __syncthreads();
    }

#pragma unroll
    for (int mt = 0; mt < 2; ++mt) {
        const int row = m0 + wm + mt * 16 + g;
#pragma unroll
        for (int nt = 0; nt < 4; ++nt) {
            const int col = n0 + wn + nt * 8 + 2 * tig;
            float b0 = 0.f, b1 = 0.f;
            if (bias) { b0 = bias[col]; b1 = bias[col + 1]; }
            float2 r0 = make_float2(acc[mt][nt][0] + b0, acc[mt][nt][1] + b1);
            float2 r1 = make_float2(acc[mt][nt][2] + b0, acc[mt][nt][3] + b1);
            if (act == 1) {
                r0.x = 1.f / (1.f + __expf(-r0.x));
                r0.y = 1.f / (1.f + __expf(-r0.y));
                r1.x = 1.f / (1.f + __expf(-r1.x));
                r1.y = 1.f / (1.f + __expf(-r1.y));
            }
            *(float2*)&C[row * Nout + col] = r0;
            *(float2*)&C[(row + 8) * Nout + col] = r1;
        }
    }
}

// ---------------- windowed attention: 4 queries per warp ----------------
// Block = 32 consecutive queries of one (b,h), 8 warps. K window (96 rows)
// staged in smem zero-padded. Aggregation loads each union-window row ONCE
// (68 rows) and feeds 4 query accumulators -> 3.8x fewer LDG wavefronts.
__global__ __launch_bounds__(256)
void attn_kernel(const float* __restrict__ q, const float* __restrict__ k,
                 const float* __restrict__ v, const float* __restrict__ x,
                 float* __restrict__ aw, float* __restrict__ xout,
                 float* __restrict__ vagg)
{
    const float scale = 0.17677669529663687f; // 1/sqrt(32)
    __shared__ __align__(16) float Ksh[96][36];
    __shared__ __align__(16) float Qsh[32][32];
    __shared__ float Psh[32][72];

    const int tid  = threadIdx.x;
    const int lane = tid & 31;
    const int wq   = tid >> 5;
    const int i0   = blockIdx.x * 32;
    const int bh   = blockIdx.y;
    const int b    = bh >> 3;
    const int hh   = bh & 7;
    const int colb = hh * HD;

    // stage K rows [i0-32, i0+63], zero for OOB (96 rows x 8 float4)
    for (int e = tid; e < 96 * 8; e += 256) {
        int r = e >> 3, j = e & 7;
        int seq = i0 + r - WIN;
        float4 val = make_float4(0.f, 0.f, 0.f, 0.f);
        if ((unsigned)seq < SEQ)
            val = *(const float4*)&k[(size_t)(b * SEQ + seq) * HDIM + colb + 4 * j];
        *(float4*)&Ksh[r][4 * j] = val;
    }
    {   // stage Q: 32 rows x 8 float4 = exactly 256 threads
        int q8 = tid >> 3, j = tid & 7;
        *(float4*)&Qsh[q8][4 * j] =
            *(const float4*)&q[(size_t)(b * SEQ + i0 + q8) * HDIM + colb + 4 * j];
    }
    __syncthreads();

    // ---- scores + softmax, one query at a time (4 per warp) ----
#pragma unroll
    for (int j = 0; j < 4; ++j) {
        const int qq = 4 * wq + j;          // local query index 0..31
        const int i  = i0 + qq;
        const float* kr0 = &Ksh[qq + lane][0];
        const float* kr1 = &Ksh[qq + lane + 32][0];
        const float* kr2 = &Ksh[qq + 64][0];
        const float* qr  = &Qsh[qq][0];
        float s0 = 0.f, s1 = 0.f, s2 = 0.f;
#pragma unroll
        for (int t = 0; t < 8; ++t) {
            float4 a  = *(const float4*)&qr[4 * t];     // broadcast
            float4 k0 = *(const float4*)&kr0[4 * t];
            float4 k1 = *(const float4*)&kr1[4 * t];
            float4 k2 = *(const float4*)&kr2[4 * t];    // broadcast
            s0 = fmaf(a.x, k0.x, fmaf(a.y, k0.y, fmaf(a.z, k0.z, fmaf(a.w, k0.w, s0))));
            s1 = fmaf(a.x, k1.x, fmaf(a.y, k1.y, fmaf(a.z, k1.z, fmaf(a.w, k1.w, s1))));
            s2 = fmaf(a.x, k2.x, fmaf(a.y, k2.y, fmaf(a.z, k2.z, fmaf(a.w, k2.w, s2))));
        }
        s0 *= scale; s1 *= scale; s2 *= scale;

        float m = fmaxf(fmaxf(s0, s1), s2);
#pragma unroll
        for (int o = 16; o; o >>= 1) m = fmaxf(m, __shfl_xor_sync(0xffffffffu, m, o));
        float e0 = __expf(s0 - m);
        float e1 = __expf(s1 - m);
        float e2 = __expf(s2 - m);
        float zz = e0 + e1 + ((lane == 0) ? e2 : 0.f);
#pragma unroll
        for (int o = 16; o; o >>= 1) zz += __shfl_xor_sync(0xffffffffu, zz, o);
        float rz = 1.0f / zz;
        float p0 = e0 * rz, p1 = e1 * rz, p2 = e2 * rz;

        int awo = (bh * SEQ + i) * WLEN;
        aw[awo + lane]      = p0;
        aw[awo + 32 + lane] = p1;
        if (lane == 0) aw[awo + 64] = p2;

        Psh[qq][lane]      = p0;
        Psh[qq][32 + lane] = p1;
        if (lane == 0) Psh[qq][64] = p2;
    }
    __syncwarp();

    // ---- aggregation: union window of 4 queries, each row loaded once ----
    const int p  = lane >> 3;
    const int d4 = (lane & 7) * 4;
    const float* base;
    int rstride;
    if (p == 0) { base = v + (size_t)(b * SEQ) * HDIM + colb + d4; rstride = HDIM; }
    else        { base = x + ((size_t)(b * SEQ) * 4 + p) * HDIM + colb + d4; rstride = 4 * HDIM; }

    const int ib = i0 + 4 * wq;                 // first query of this warp
    const float* prow = &Psh[4 * wq][0];        // query j -> prow + j*72

    float4 acc[4];
#pragma unroll
    for (int j = 0; j < 4; ++j) acc[j] = make_float4(0.f, 0.f, 0.f, 0.f);

    if (ib >= WIN && ib <= SEQ - 36) {
        // fast path: all 68 rows in range; masks resolved at compile time
        const float* ptr = base + (size_t)(ib - WIN) * rstride;
        // prologue w=0..2
#pragma unroll
        for (int w = 0; w < 3; ++w) {
            float4 vv = *(const float4*)ptr; ptr += rstride;
#pragma unroll
            for (int j = 0; j < 4; ++j) {
                if (w - j >= 0) {
                    float pw = prow[j * 72 + (w - j)];
                    acc[j].x = fmaf(pw, vv.x, acc[j].x);
                    acc[j].y = fmaf(pw, vv.y, acc[j].y);
                    acc[j].z = fmaf(pw, vv.z, acc[j].z);
                    acc[j].w = fmaf(pw, vv.w, acc[j].w);
                }
            }
        }
        // main w=3..64: all 4 queries active
#pragma unroll 4
        for (int w = 3; w < 65; ++w) {
            float4 vv = *(const float4*)ptr; ptr += rstride;
#pragma unroll
            for (int j = 0; j < 4; ++j) {
                float pw = prow[j * 72 + (w - j)];
                acc[j].x = fmaf(pw, vv.x, acc[j].x);
                acc[j].y = fmaf(pw, vv.y, acc[j].y);
                acc[j].z = fmaf(pw, vv.z, acc[j].z);
                acc[j].w = fmaf(pw, vv.w, acc[j].w);
            }
        }
        // epilogue w=65..67
#pragma unroll
        for (int w = 65; w < 68; ++w) {
            float4 vv = *(const float4*)ptr; ptr += rstride;
#pragma unroll
            for (int j = 0; j < 4; ++j) {
                if (w - j < 65) {
                    float pw = prow[j * 72 + (w - j)];
                    acc[j].x = fmaf(pw, vv.x, acc[j].x);
                    acc[j].y = fmaf(pw, vv.y, acc[j].y);
                    acc[j].z = fmaf(pw, vv.z, acc[j].z);
                    acc[j].w = fmaf(pw, vv.w, acc[j].w);
                }
            }
        }
    } else {
        // boundary path: guard row range (OOB rows contribute 0, like reference)
        for (int w = 0; w < 68; ++w) {
            int row = ib - WIN + w;
            if ((unsigned)row >= SEQ) continue;
            float4 vv = *(const float4*)(base + (size_t)row * rstride);
#pragma unroll
            for (int j = 0; j < 4; ++j) {
                int wj = w - j;
                if (wj >= 0 && wj < WLEN) {
                    float pw = prow[j * 72 + wj];
                    acc[j].x = fmaf(pw, vv.x, acc[j].x);
                    acc[j].y = fmaf(pw, vv.y, acc[j].y);
                    acc[j].z = fmaf(pw, vv.z, acc[j].z);
                    acc[j].w = fmaf(pw, vv.w, acc[j].w);
                }
            }
        }
    }

#pragma unroll
    for (int j = 0; j < 4; ++j) {
        const int i = ib + j;
        if (p == 0)
            *(float4*)&xout[(size_t)(b * SEQ + i) * HDIM + colb + d4] = acc[j];
        else
            *(float4*)&vagg[((size_t)(b * SEQ + i) * 3 + (p - 1)) * HDIM + colb + d4] = acc[j];
    }
}

// ---------------- vec_dot + vec_norm + invariants (fused) ----------------
__global__ __launch_bounds__(256)
void reduce_inv_kernel(const float* __restrict__ vp, const float* __restrict__ x,
                       const float* __restrict__ ad, const float* __restrict__ an,
                       float* __restrict__ vd, float* __restrict__ vn,
                       float* __restrict__ inv)
{
    int idx = blockIdx.x * 256 + threadIdx.x;   // 4096*256
    int bn = idx >> 8, j = idx & 255;
    const float* r = vp + bn * 1536;            // 3 rows of 512
    float dot = r[j] * r[256 + j] + r[512 + j] * r[768 + j] + r[1024 + j] * r[1280 + j];
    const float* xr = x + (bn * 4 + 1) * 256 + j;
    float v0 = xr[0], v1 = xr[256], v2 = xr[512];
    float nrm = sqrtf(v0 * v0 + v1 * v1 + v2 * v2);
    vd[idx] = dot;
    vn[idx] = nrm;
    inv[bn * 512 + j]       = ad[0] * dot;
    inv[bn * 512 + 256 + j] = an[0] * nrm;
}

// ---------------- final epilogue ----------------
__global__ __launch_bounds__(256)
void final_kernel(const float* __restrict__ vd, const float* __restrict__ vn,
                  const float* __restrict__ o, const float* __restrict__ gate,
                  const float* __restrict__ vagg, const float* __restrict__ x,
                  float* __restrict__ out)
{
    int idx = blockIdx.x * 256 + threadIdx.x;   // 4096*256
    int bn = idx >> 8, j = idx & 255;
    const float* orow = o + bn * 768;
    float vdv = vd[idx], vnv = vn[idx];
    out[(bn * 4) * 256 + j] = vdv * orow[j] + vnv * orow[256 + j] + orow[512 + j];
    float g = gate[idx];
#pragma unroll
    for (int c = 0; c < 3; ++c) {
        int xoff = (bn * 4 + 1 + c) * 256 + j;
        out[xoff] = g * vagg[(bn * 3 + c) * 256 + j] + x[xoff];
    }
}

// ---------------- launch ----------------
extern "C" void kernel_launch(void* const* d_in, const int* in_sizes, int n_in,
                              void* d_out, int out_size)
{
    const float* x    = (const float*)d_in[0];
    const float* Wq   = (const float*)d_in[1];
    const float* bq   = (const float*)d_in[2];
    const float* Wk   = (const float*)d_in[3];
    const float* bk   = (const float*)d_in[4];
    const float* Wv   = (const float*)d_in[5];
    const float* bv   = (const float*)d_in[6];
    const float* Wo   = (const float*)d_in[7];
    const float* bo   = (const float*)d_in[8];
    const float* Wvec = (const float*)d_in[9];
    const float* ad   = (const float*)d_in[10];
    const float* an   = (const float*)d_in[11];
    const float* Wg   = (const float*)d_in[12];
    const float* bg   = (const float*)d_in[13];

    float* S;
    cudaGetSymbolAddress((void**)&S, g_scratch);
    float* out = (float*)d_out;
    float* aw  = out + BATCH * SEQ * 4 * HDIM;   // x_final first, then attn_weights

    const int M = BATCH * SEQ;   // 4096

    // q,k,v = x_scalar @ W + b  (fused via blockIdx.z)
    mma_gemm<<<dim3(4, 32, 3), 256>>>(x, Wq, Wk, Wv, bq, bk, bv,
                                      S + OFF_Q, 1048576, M, 256, 256, 1, 0);
    // vec_proj = vec @ Wvec   (12288 x 512)
    mma_gemm<<<dim3(8, 96, 1), 256>>>(x, Wvec, Wvec, Wvec, nullptr, nullptr, nullptr,
                                      S + OFF_VP, 0, 3 * M, 512, 256, 2, 0);
    // vec_dot, vec_norm, invariants
    reduce_inv_kernel<<<M, 256>>>(S + OFF_VP, x, ad, an,
                                  S + OFF_VD, S + OFF_VN, S + OFF_INV);
    // windowed attention (writes attn_weights, x_out, vec_aggr)
    attn_kernel<<<dim3(SEQ / 32, 16), 256>>>(S + OFF_Q, S + OFF_K, S + OFF_V, x, aw,
                                             S + OFF_XOUT, S + OFF_VAGG);
    // o = x_out @ Wo + bo
    mma_gemm<<<dim3(12, 32, 1), 256>>>(S + OFF_XOUT, Wo, Wo, Wo, bo, bo, bo,
                                       S + OFF_O, 0, M, 768, 256, 0, 0);
    // gate = sigmoid(inv @ Wg + bg)
    mma_gemm<<<dim3(4, 32, 1), 256>>>(S + OFF_INV, Wg, Wg, Wg, bg, bg, bg,
                                      S + OFF_GATE, 0, M, 256, 512, 0, 1);
    // final outputs
    final_kernel<<<M, 256>>>(S + OFF_VD, S + OFF_VN, S + OFF_O, S + OFF_GATE,
                             S + OFF_VAGG, x, out);
}

// round 12
// speedup vs baseline: 3.2726x; 1.0277x over previous
#include <cuda_runtime.h>
#include <math.h>

#define BATCH 2
#define SEQ   2048
#define HDIM  256
#define NHEAD 8
#define HD    32
#define WIN   32
#define WLEN  65

// ---------------- scratch (static __device__, no allocation) ----------------
#define OFF_Q     0
#define OFF_K     1048576
#define OFF_V     2097152
#define OFF_VP    3145728      // vec_proj 12288x512
#define OFF_VD    9437184      // vec_dot 4096x256
#define OFF_VN    10485760     // vec_norm 4096x256
#define OFF_INV   11534336     // invariants 4096x512
#define OFF_XOUT  13631488     // 4096x256
#define OFF_VAGG  14680064     // 4096x3x256
#define OFF_O     17825792     // 4096x768
#define OFF_GATE  20971520     // 4096x256
#define SCRATCH_FLOATS 22020096

__device__ float g_scratch[SCRATCH_FLOATS];

// round-to-nearest fp32 -> tf32
__device__ __forceinline__ float tf32r(float x) {
    unsigned u;
    asm("cvt.rna.tf32.f32 %0, %1;" : "=r"(u) : "f"(x));
    return __uint_as_float(u);
}
__device__ __forceinline__ float4 tf32r4(float4 v) {
    return make_float4(tf32r(v.x), tf32r(v.y), tf32r(v.z), tf32r(v.w));
}

// ---------------- TF32 tensor-core GEMM, 2-stage smem double buffer --------
// Block tile 128x64, K-step 32, 8 warps; warp tile 32x32 via 8x m16n8k8 mma.
// Dynamic smem: As[2][128][36] + Bs[2][32][72] = 55296 B.
#define AS(s, m, kk) dsm[(s) * 4608 + (m) * 36 + (kk)]
#define BS(s, kk, n) dsm[9216 + (s) * 2304 + (kk) * 72 + (n)]

__global__ __launch_bounds__(256)
void mma_gemm(const float* __restrict__ A,
              const float* __restrict__ B0, const float* __restrict__ B1,
              const float* __restrict__ B2,
              const float* __restrict__ c0, const float* __restrict__ c1,
              const float* __restrict__ c2,
              float* __restrict__ C, int Cstride,
              int M, int Nout, int K, int amode, int act)
{
    extern __shared__ __align__(16) float dsm[];

    const int z = blockIdx.z;
    const float* Bm   = (z == 0) ? B0 : (z == 1) ? B1 : B2;
    const float* bias = (z == 0) ? c0 : (z == 1) ? c1 : c2;
    C += (size_t)z * Cstride;

    const int tid  = threadIdx.x;
    const int lane = tid & 31;
    const int warp = tid >> 5;
    const int g    = lane >> 2;
    const int tig  = lane & 3;
    const int wm   = (warp & 3) * 32;
    const int wn   = (warp >> 2) * 32;
    const int m0   = blockIdx.y * 128;
    const int n0   = blockIdx.x * 64;

    const int rA = tid >> 1;
    const int kc = (tid & 1) * 16;
    const int rowA = m0 + rA;
    int aoff;
    if (amode == 1)      aoff = rowA * 1024;
    else if (amode == 2) { int t = rowA / 3; int c = rowA - 3 * t; aoff = (4 * t + 1 + c) * 256; }
    else                 aoff = rowA * K;

    const int kB = tid >> 3;
    const int nB = (tid & 7) * 8;

    float4 pa[4];
    float4 pb[2];
    {   // prefetch tile 0
        const float* ap = A + aoff + kc;
#pragma unroll
        for (int j = 0; j < 4; ++j) pa[j] = *(const float4*)(ap + j * 4);
        const float* bp = Bm + kB * Nout + n0 + nB;
        pb[0] = *(const float4*)bp;
        pb[1] = *(const float4*)(bp + 4);
    }
    // store tile 0 into stage 0
#pragma unroll
    for (int j = 0; j < 4; ++j)
        *(float4*)&AS(0, rA, kc + j * 4) = tf32r4(pa[j]);
    *(float4*)&BS(0, kB, nB)     = tf32r4(pb[0]);
    *(float4*)&BS(0, kB, nB + 4) = tf32r4(pb[1]);

    float acc[2][4][4];
#pragma unroll
    for (int mt = 0; mt < 2; ++mt)
#pragma unroll
        for (int nt = 0; nt < 4; ++nt)
#pragma unroll
            for (int r = 0; r < 4; ++r) acc[mt][nt][r] = 0.f;

    const int NT = K >> 5;
    int st = 0;
    for (int kt = 0; kt < NT; ++kt) {
        __syncthreads();
        const bool more = (kt + 1 < NT);
        if (more) {   // prefetch next tile into registers
            const int k1 = (kt + 1) << 5;
            const float* ap = A + aoff + k1 + kc;
#pragma unroll
            for (int j = 0; j < 4; ++j) pa[j] = *(const float4*)(ap + j * 4);
            const float* bp = Bm + (k1 + kB) * Nout + n0 + nB;
            pb[0] = *(const float4*)bp;
            pb[1] = *(const float4*)(bp + 4);
        }

        // MMA on stage st
#pragma unroll
        for (int kq = 0; kq < 4; ++kq) {
            const int kk = kq * 8;
            unsigned a[2][4], b[4][2];
#pragma unroll
            for (int mt = 0; mt < 2; ++mt) {
                const int mr = wm + mt * 16 + g;
                a[mt][0] = __float_as_uint(AS(st, mr, kk + tig));
                a[mt][1] = __float_as_uint(AS(st, mr + 8, kk + tig));
                a[mt][2] = __float_as_uint(AS(st, mr, kk + tig + 4));
                a[mt][3] = __float_as_uint(AS(st, mr + 8, kk + tig + 4));
            }
#pragma unroll
            for (int nt = 0; nt < 4; ++nt) {
                const int nc = wn + nt * 8 + g;
                b[nt][0] = __float_as_uint(BS(st, kk + tig, nc));
                b[nt][1] = __float_as_uint(BS(st, kk + tig + 4, nc));
            }
#pragma unroll
            for (int mt = 0; mt < 2; ++mt)
#pragma unroll
                for (int nt = 0; nt < 4; ++nt)
                    asm volatile(
                        "mma.sync.aligned.m16n8k8.row.col.f32.tf32.tf32.f32 "
                        "{%0,%1,%2,%3}, {%4,%5,%6,%7}, {%8,%9}, {%0,%1,%2,%3};"
                        : "+f"(acc[mt][nt][0]), "+f"(acc[mt][nt][1]),
                          "+f"(acc[mt][nt][2]), "+f"(acc[mt][nt][3])
                        : "r"(a[mt][0]), "r"(a[mt][1]), "r"(a[mt][2]), "r"(a[mt][3]),
                          "r"(b[nt][0]), "r"(b[nt][1]));
        }

        if (more) {   // store next tile into the other stage (no sync needed:
                      // all warps passed the sync above, so prior MMA on st^1 done)
            const int s2 = st ^ 1;
#pragma unroll
            for (int j = 0; j < 4; ++j)
                *(float4*)&AS(s2, rA, kc + j * 4) = tf32r4(pa[j]);
            *(float4*)&BS(s2, kB, nB)     = tf32r4(pb[0]);
            *(float4*)&BS(s2, kB, nB + 4) = tf32r4(pb[1]);
        }
        st ^= 1;
    }

    // epilogue
#pragma unroll
    for (int mt = 0; mt < 2; ++mt) {
        const int row = m0 + wm + mt * 16 + g;
#pragma unroll
        for (int nt = 0; nt < 4; ++nt) {
            const int col = n0 + wn + nt * 8 + 2 * tig;
            float b0 = 0.f, b1 = 0.f;
            if (bias) { b0 = bias[col]; b1 = bias[col + 1]; }
            float2 r0 = make_float2(acc[mt][nt][0] + b0, acc[mt][nt][1] + b1);
            float2 r1 = make_float2(acc[mt][nt][2] + b0, acc[mt][nt][3] + b1);
            if (act == 1) {
                r0.x = 1.f / (1.f + __expf(-r0.x));
                r0.y = 1.f / (1.f + __expf(-r0.y));
                r1.x = 1.f / (1.f + __expf(-r1.x));
                r1.y = 1.f / (1.f + __expf(-r1.y));
            }
            *(float2*)&C[row * Nout + col] = r0;
            *(float2*)&C[(row + 8) * Nout + col] = r1;
        }
    }
}

// ---------------- windowed attention: 4 queries per warp, batched loads ----
__global__ __launch_bounds__(256)
void attn_kernel(const float* __restrict__ q, const float* __restrict__ k,
                 const float* __restrict__ v, const float* __restrict__ x,
                 float* __restrict__ aw, float* __restrict__ xout,
                 float* __restrict__ vagg)
{
    const float scale = 0.17677669529663687f; // 1/sqrt(32)
    __shared__ __align__(16) float Ksh[96][36];
    __shared__ __align__(16) float Qsh[32][32];
    __shared__ float Psh[32][72];

    const int tid  = threadIdx.x;
    const int lane = tid & 31;
    const int wq   = tid >> 5;
    const int i0   = blockIdx.x * 32;
    const int bh   = blockIdx.y;
    const int b    = bh >> 3;
    const int hh   = bh & 7;
    const int colb = hh * HD;

    // stage K rows [i0-32, i0+63], zero for OOB
    for (int e = tid; e < 96 * 8; e += 256) {
        int r = e >> 3, j = e & 7;
        int seq = i0 + r - WIN;
        float4 val = make_float4(0.f, 0.f, 0.f, 0.f);
        if ((unsigned)seq < SEQ)
            val = *(const float4*)&k[(size_t)(b * SEQ + seq) * HDIM + colb + 4 * j];
        *(float4*)&Ksh[r][4 * j] = val;
    }
    {   // stage Q
        int q8 = tid >> 3, j = tid & 7;
        *(float4*)&Qsh[q8][4 * j] =
            *(const float4*)&q[(size_t)(b * SEQ + i0 + q8) * HDIM + colb + 4 * j];
    }
    __syncthreads();

    // ---- scores + softmax (4 queries per warp) ----
#pragma unroll
    for (int j = 0; j < 4; ++j) {
        const int qq = 4 * wq + j;
        const int i  = i0 + qq;
        const float* kr0 = &Ksh[qq + lane][0];
        const float* kr1 = &Ksh[qq + lane + 32][0];
        const float* kr2 = &Ksh[qq + 64][0];
        const float* qr  = &Qsh[qq][0];
        float s0 = 0.f, s1 = 0.f, s2 = 0.f;
#pragma unroll
        for (int t = 0; t < 8; ++t) {
            float4 a  = *(const float4*)&qr[4 * t];
            float4 k0 = *(const float4*)&kr0[4 * t];
            float4 k1 = *(const float4*)&kr1[4 * t];
            float4 k2 = *(const float4*)&kr2[4 * t];
            s0 = fmaf(a.x, k0.x, fmaf(a.y, k0.y, fmaf(a.z, k0.z, fmaf(a.w, k0.w, s0))));
            s1 = fmaf(a.x, k1.x, fmaf(a.y, k1.y, fmaf(a.z, k1.z, fmaf(a.w, k1.w, s1))));
            s2 = fmaf(a.x, k2.x, fmaf(a.y, k2.y, fmaf(a.z, k2.z, fmaf(a.w, k2.w, s2))));
        }
        s0 *= scale; s1 *= scale; s2 *= scale;

        float m = fmaxf(fmaxf(s0, s1), s2);
#pragma unroll
        for (int o = 16; o; o >>= 1) m = fmaxf(m, __shfl_xor_sync(0xffffffffu, m, o));
        float e0 = __expf(s0 - m);
        float e1 = __expf(s1 - m);
        float e2 = __expf(s2 - m);
        float zz = e0 + e1 + ((lane == 0) ? e2 : 0.f);
#pragma unroll
        for (int o = 16; o; o >>= 1) zz += __shfl_xor_sync(0xffffffffu, zz, o);
        float rz = 1.0f / zz;
        float p0 = e0 * rz, p1 = e1 * rz, p2 = e2 * rz;

        int awo = (bh * SEQ + i) * WLEN;
        aw[awo + lane]      = p0;
        aw[awo + 32 + lane] = p1;
        if (lane == 0) aw[awo + 64] = p2;

        Psh[qq][lane]      = p0;
        Psh[qq][32 + lane] = p1;
        if (lane == 0) Psh[qq][64] = p2;
    }
    __syncwarp();

    // ---- aggregation: union window, 4-row load batches (MLP >= 4) ----
    const int p  = lane >> 3;
    const int d4 = (lane & 7) * 4;
    const float* base;
    int rstride;
    if (p == 0) { base = v + (size_t)(b * SEQ) * HDIM + colb + d4; rstride = HDIM; }
    else        { base = x + ((size_t)(b * SEQ) * 4 + p) * HDIM + colb + d4; rstride = 4 * HDIM; }

    const int ib = i0 + 4 * wq;
    const float* prow = &Psh[4 * wq][0];

    float4 acc[4];
#pragma unroll
    for (int j = 0; j < 4; ++j) acc[j] = make_float4(0.f, 0.f, 0.f, 0.f);

#define AGG_FMA(jj, ww, vv)                                             \
    {                                                                   \
        float pw = prow[(jj) * 72 + (ww) - (jj)];                       \
        acc[jj].x = fmaf(pw, (vv).x, acc[jj].x);                        \
        acc[jj].y = fmaf(pw, (vv).y, acc[jj].y);                        \
        acc[jj].z = fmaf(pw, (vv).z, acc[jj].z);                        \
        acc[jj].w = fmaf(pw, (vv).w, acc[jj].w);                        \
    }

    if (ib >= WIN && ib <= SEQ - 36) {
        const float* ptr = base + (size_t)(ib - WIN) * rstride;
        float4 vv[4];
        // prologue w=0..3 (guard j<=w)
#pragma unroll
        for (int t = 0; t < 4; ++t) { vv[t] = *(const float4*)ptr; ptr += rstride; }
#pragma unroll
        for (int w = 0; w < 4; ++w)
#pragma unroll
            for (int j = 0; j < 4; ++j)
                if (j <= w) AGG_FMA(j, w, vv[w]);
        // main w=4..63: 15 chunks of 4, all queries active
        for (int w0 = 4; w0 < 64; w0 += 4) {
#pragma unroll
            for (int t = 0; t < 4; ++t) { vv[t] = *(const float4*)ptr; ptr += rstride; }
#pragma unroll
            for (int t = 0; t < 4; ++t)
#pragma unroll
                for (int j = 0; j < 4; ++j)
                    AGG_FMA(j, w0 + t, vv[t]);
        }
        // epilogue w=64..67 (guard w-j < 65)
#pragma unroll
        for (int t = 0; t < 4; ++t) { vv[t] = *(const float4*)ptr; ptr += rstride; }
#pragma unroll
        for (int w = 64; w < 68; ++w)
#pragma unroll
            for (int j = 0; j < 4; ++j)
                if (w - j < WLEN) AGG_FMA(j, w, vv[w - 64]);
    } else {
        // boundary path
        for (int w = 0; w < 68; ++w) {
            int row = ib - WIN + w;
            if ((unsigned)row >= SEQ) continue;
            float4 vv = *(const float4*)(base + (size_t)row * rstride);
#pragma unroll
            for (int j = 0; j < 4; ++j) {
                int wj = w - j;
                if (wj >= 0 && wj < WLEN) AGG_FMA(j, w, vv);
            }
        }
    }
#undef AGG_FMA

#pragma unroll
    for (int j = 0; j < 4; ++j) {
        const int i = ib + j;
        if (p == 0)
            *(float4*)&xout[(size_t)(b * SEQ + i) * HDIM + colb + d4] = acc[j];
        else
            *(float4*)&vagg[((size_t)(b * SEQ + i) * 3 + (p - 1)) * HDIM + colb + d4] = acc[j];
    }
}

// ---------------- vec_dot + vec_norm + invariants (fused) ----------------
__global__ __launch_bounds__(256)
void reduce_inv_kernel(const float* __restrict__ vp, const float* __restrict__ x,
                       const float* __restrict__ ad, const float* __restrict__ an,
                       float* __restrict__ vd, float* __restrict__ vn,
                       float* __restrict__ inv)
{
    int idx = blockIdx.x * 256 + threadIdx.x;   // 4096*256
    int bn = idx >> 8, j = idx & 255;
    const float* r = vp + bn * 1536;
    float dot = r[j] * r[256 + j] + r[512 + j] * r[768 + j] + r[1024 + j] * r[1280 + j];
    const float* xr = x + (bn * 4 + 1) * 256 + j;
    float v0 = xr[0], v1 = xr[256], v2 = xr[512];
    float nrm = sqrtf(v0 * v0 + v1 * v1 + v2 * v2);
    vd[idx] = dot;
    vn[idx] = nrm;
    inv[bn * 512 + j]       = ad[0] * dot;
    inv[bn * 512 + 256 + j] = an[0] * nrm;
}

// ---------------- final epilogue ----------------
__global__ __launch_bounds__(256)
void final_kernel(const float* __restrict__ vd, const float* __restrict__ vn,
                  const float* __restrict__ o, const float* __restrict__ gate,
                  const float* __restrict__ vagg, const float* __restrict__ x,
                  float* __restrict__ out)
{
    int idx = blockIdx.x * 256 + threadIdx.x;   // 4096*256
    int bn = idx >> 8, j = idx & 255;
    const float* orow = o + bn * 768;
    float vdv = vd[idx], vnv = vn[idx];
    out[(bn * 4) * 256 + j] = vdv * orow[j] + vnv * orow[256 + j] + orow[512 + j];
    float g = gate[idx];
#pragma unroll
    for (int c = 0; c < 3; ++c) {
        int xoff = (bn * 4 + 1 + c) * 256 + j;
        out[xoff] = g * vagg[(bn * 3 + c) * 256 + j] + x[xoff];
    }
}

// ---------------- launch ----------------
extern "C" void kernel_launch(void* const* d_in, const int* in_sizes, int n_in,
                              void* d_out, int out_size)
{
    const float* x    = (const float*)d_in[0];
    const float* Wq   = (const float*)d_in[1];
    const float* bq   = (const float*)d_in[2];
    const float* Wk   = (const float*)d_in[3];
    const float* bk   = (const float*)d_in[4];
    const float* Wv   = (const float*)d_in[5];
    const float* bv   = (const float*)d_in[6];
    const float* Wo   = (const float*)d_in[7];
    const float* bo   = (const float*)d_in[8];
    const float* Wvec = (const float*)d_in[9];
    const float* ad   = (const float*)d_in[10];
    const float* an   = (const float*)d_in[11];
    const float* Wg   = (const float*)d_in[12];
    const float* bg   = (const float*)d_in[13];

    float* S;
    cudaGetSymbolAddress((void**)&S, g_scratch);
    float* out = (float*)d_out;
    float* aw  = out + BATCH * SEQ * 4 * HDIM;

    const int M = BATCH * SEQ;   // 4096
    const int SMEM = 55296;      // 2-stage As + Bs

    cudaFuncSetAttribute(mma_gemm, cudaFuncAttributeMaxDynamicSharedMemorySize, SMEM);

    // q,k,v = x_scalar @ W + b  (fused via blockIdx.z)
    mma_gemm<<<dim3(4, 32, 3), 256, SMEM>>>(x, Wq, Wk, Wv, bq, bk, bv,
                                            S + OFF_Q, 1048576, M, 256, 256, 1, 0);
    // vec_proj = vec @ Wvec   (12288 x 512)
    mma_gemm<<<dim3(8, 96, 1), 256, SMEM>>>(x, Wvec, Wvec, Wvec, nullptr, nullptr, nullptr,
                                            S + OFF_VP, 0, 3 * M, 512, 256, 2, 0);
    // vec_dot, vec_norm, invariants
    reduce_inv_kernel<<<M, 256>>>(S + OFF_VP, x, ad, an,
                                  S + OFF_VD, S + OFF_VN, S + OFF_INV);
    // windowed attention
    attn_kernel<<<dim3(SEQ / 32, 16), 256>>>(S + OFF_Q, S + OFF_K, S + OFF_V, x, aw,
                                             S + OFF_XOUT, S + OFF_VAGG);
    // o = x_out @ Wo + bo
    mma_gemm<<<dim3(12, 32, 1), 256, SMEM>>>(S + OFF_XOUT, Wo, Wo, Wo, bo, bo, bo,
                                             S + OFF_O, 0, M, 768, 256, 0, 0);
    // gate = sigmoid(inv @ Wg + bg)
    mma_gemm<<<dim3(4, 32, 1), 256, SMEM>>>(S + OFF_INV, Wg, Wg, Wg, bg, bg, bg,
                                            S + OFF_GATE, 0, M, 256, 512, 0, 1);
    // final outputs
    final_kernel<<<M, 256>>>(S + OFF_VD, S + OFF_VN, S + OFF_O, S + OFF_GATE,
                             S + OFF_VAGG, x, out);
}

// round 13
// speedup vs baseline: 3.7269x; 1.1388x over previous
#include <cuda_runtime.h>
#include <math.h>

#define BATCH 2
#define SEQ   2048
#define HDIM  256
#define NHEAD 8
#define HD    32
#define WIN   32
#define WLEN  65

// ---------------- scratch (static __device__, no allocation) ----------------
#define OFF_Q     0
#define OFF_K     1048576
#define OFF_V     2097152
#define OFF_VP    3145728      // vec_proj 12288x512
#define OFF_VD    9437184      // vec_dot 4096x256
#define OFF_VN    10485760     // vec_norm 4096x256
#define OFF_INV   11534336     // invariants 4096x512
#define OFF_XOUT  13631488     // 4096x256
#define OFF_VAGG  14680064     // 4096x3x256
#define OFF_O     17825792     // 4096x768
#define OFF_GATE  20971520     // 4096x256
#define SCRATCH_FLOATS 22020096

__device__ float g_scratch[SCRATCH_FLOATS];

// round-to-nearest fp32 -> tf32
__device__ __forceinline__ float tf32r(float x) {
    unsigned u;
    asm("cvt.rna.tf32.f32 %0, %1;" : "=r"(u) : "f"(x));
    return __uint_as_float(u);
}
__device__ __forceinline__ float4 tf32r4(float4 v) {
    return make_float4(tf32r(v.x), tf32r(v.y), tf32r(v.z), tf32r(v.w));
}

// ---------------- TF32 tensor-core GEMM, 2-stage smem double buffer --------
#define AS(s, m, kk) dsm[(s) * 4608 + (m) * 36 + (kk)]
#define BS(s, kk, n) dsm[9216 + (s) * 2304 + (kk) * 72 + (n)]

__global__ __launch_bounds__(256)
void mma_gemm(const float* __restrict__ A,
              const float* __restrict__ B0, const float* __restrict__ B1,
              const float* __restrict__ B2,
              const float* __restrict__ c0, const float* __restrict__ c1,
              const float* __restrict__ c2,
              float* __restrict__ C, int Cstride,
              int M, int Nout, int K, int amode, int act)
{
    extern __shared__ __align__(16) float dsm[];

    const int z = blockIdx.z;
    const float* Bm   = (z == 0) ? B0 : (z == 1) ? B1 : B2;
    const float* bias = (z == 0) ? c0 : (z == 1) ? c1 : c2;
    C += (size_t)z * Cstride;

    const int tid  = threadIdx.x;
    const int lane = tid & 31;
    const int warp = tid >> 5;
    const int g    = lane >> 2;
    const int tig  = lane & 3;
    const int wm   = (warp & 3) * 32;
    const int wn   = (warp >> 2) * 32;
    const int m0   = blockIdx.y * 128;
    const int n0   = blockIdx.x * 64;

    const int rA = tid >> 1;
    const int kc = (tid & 1) * 16;
    const int rowA = m0 + rA;
    int aoff;
    if (amode == 1)      aoff = rowA * 1024;
    else if (amode == 2) { int t = rowA / 3; int c = rowA - 3 * t; aoff = (4 * t + 1 + c) * 256; }
    else                 aoff = rowA * K;

    const int kB = tid >> 3;
    const int nB = (tid & 7) * 8;

    float4 pa[4];
    float4 pb[2];
    {
        const float* ap = A + aoff + kc;
#pragma unroll
        for (int j = 0; j < 4; ++j) pa[j] = *(const float4*)(ap + j * 4);
        const float* bp = Bm + kB * Nout + n0 + nB;
        pb[0] = *(const float4*)bp;
        pb[1] = *(const float4*)(bp + 4);
    }
#pragma unroll
    for (int j = 0; j < 4; ++j)
        *(float4*)&AS(0, rA, kc + j * 4) = tf32r4(pa[j]);
    *(float4*)&BS(0, kB, nB)     = tf32r4(pb[0]);
    *(float4*)&BS(0, kB, nB + 4) = tf32r4(pb[1]);

    float acc[2][4][4];
#pragma unroll
    for (int mt = 0; mt < 2; ++mt)
#pragma unroll
        for (int nt = 0; nt < 4; ++nt)
#pragma unroll
            for (int r = 0; r < 4; ++r) acc[mt][nt][r] = 0.f;

    const int NT = K >> 5;
    int st = 0;
    for (int kt = 0; kt < NT; ++kt) {
        __syncthreads();
        const bool more = (kt + 1 < NT);
        if (more) {
            const int k1 = (kt + 1) << 5;
            const float* ap = A + aoff + k1 + kc;
#pragma unroll
            for (int j = 0; j < 4; ++j) pa[j] = *(const float4*)(ap + j * 4);
            const float* bp = Bm + (k1 + kB) * Nout + n0 + nB;
            pb[0] = *(const float4*)bp;
            pb[1] = *(const float4*)(bp + 4);
        }

#pragma unroll
        for (int kq = 0; kq < 4; ++kq) {
            const int kk = kq * 8;
            unsigned a[2][4], b[4][2];
#pragma unroll
            for (int mt = 0; mt < 2; ++mt) {
                const int mr = wm + mt * 16 + g;
                a[mt][0] = __float_as_uint(AS(st, mr, kk + tig));
                a[mt][1] = __float_as_uint(AS(st, mr + 8, kk + tig));
                a[mt][2] = __float_as_uint(AS(st, mr, kk + tig + 4));
                a[mt][3] = __float_as_uint(AS(st, mr + 8, kk + tig + 4));
            }
#pragma unroll
            for (int nt = 0; nt < 4; ++nt) {
                const int nc = wn + nt * 8 + g;
                b[nt][0] = __float_as_uint(BS(st, kk + tig, nc));
                b[nt][1] = __float_as_uint(BS(st, kk + tig + 4, nc));
            }
#pragma unroll
            for (int mt = 0; mt < 2; ++mt)
#pragma unroll
                for (int nt = 0; nt < 4; ++nt)
                    asm volatile(
                        "mma.sync.aligned.m16n8k8.row.col.f32.tf32.tf32.f32 "
                        "{%0,%1,%2,%3}, {%4,%5,%6,%7}, {%8,%9}, {%0,%1,%2,%3};"
                        : "+f"(acc[mt][nt][0]), "+f"(acc[mt][nt][1]),
                          "+f"(acc[mt][nt][2]), "+f"(acc[mt][nt][3])
                        : "r"(a[mt][0]), "r"(a[mt][1]), "r"(a[mt][2]), "r"(a[mt][3]),
                          "r"(b[nt][0]), "r"(b[nt][1]));
        }

        if (more) {
            const int s2 = st ^ 1;
#pragma unroll
            for (int j = 0; j < 4; ++j)
                *(float4*)&AS(s2, rA, kc + j * 4) = tf32r4(pa[j]);
            *(float4*)&BS(s2, kB, nB)     = tf32r4(pb[0]);
            *(float4*)&BS(s2, kB, nB + 4) = tf32r4(pb[1]);
        }
        st ^= 1;
    }

#pragma unroll
    for (int mt = 0; mt < 2; ++mt) {
        const int row = m0 + wm + mt * 16 + g;
#pragma unroll
        for (int nt = 0; nt < 4; ++nt) {
            const int col = n0 + wn + nt * 8 + 2 * tig;
            float b0 = 0.f, b1 = 0.f;
            if (bias) { b0 = bias[col]; b1 = bias[col + 1]; }
            float2 r0 = make_float2(acc[mt][nt][0] + b0, acc[mt][nt][1] + b1);
            float2 r1 = make_float2(acc[mt][nt][2] + b0, acc[mt][nt][3] + b1);
            if (act == 1) {
                r0.x = 1.f / (1.f + __expf(-r0.x));
                r0.y = 1.f / (1.f + __expf(-r0.y));
                r1.x = 1.f / (1.f + __expf(-r1.x));
                r1.y = 1.f / (1.f + __expf(-r1.y));
            }
            *(float2*)&C[row * Nout + col] = r0;
            *(float2*)&C[(row + 8) * Nout + col] = r1;
        }
    }
}

// ---------------- windowed attention: 4 queries per warp, batched loads ----
__global__ __launch_bounds__(256)
void attn_kernel(const float* __restrict__ q, const float* __restrict__ k,
                 const float* __restrict__ v, const float* __restrict__ x,
                 float* __restrict__ aw, float* __restrict__ xout,
                 float* __restrict__ vagg)
{
    const float scale = 0.17677669529663687f; // 1/sqrt(32)
    __shared__ __align__(16) float Ksh[96][36];
    __shared__ __align__(16) float Qsh[32][32];
    __shared__ float Psh[32][72];

    const int tid  = threadIdx.x;
    const int lane = tid & 31;
    const int wq   = tid >> 5;
    const int i0   = blockIdx.x * 32;
    const int bh   = blockIdx.y;
    const int b    = bh >> 3;
    const int hh   = bh & 7;
    const int colb = hh * HD;

    for (int e = tid; e < 96 * 8; e += 256) {
        int r = e >> 3, j = e & 7;
        int seq = i0 + r - WIN;
        float4 val = make_float4(0.f, 0.f, 0.f, 0.f);
        if ((unsigned)seq < SEQ)
            val = *(const float4*)&k[(size_t)(b * SEQ + seq) * HDIM + colb + 4 * j];
        *(float4*)&Ksh[r][4 * j] = val;
    }
    {
        int q8 = tid >> 3, j = tid & 7;
        *(float4*)&Qsh[q8][4 * j] =
            *(const float4*)&q[(size_t)(b * SEQ + i0 + q8) * HDIM + colb + 4 * j];
    }
    __syncthreads();

#pragma unroll
    for (int j = 0; j < 4; ++j) {
        const int qq = 4 * wq + j;
        const int i  = i0 + qq;
        const float* kr0 = &Ksh[qq + lane][0];
        const float* kr1 = &Ksh[qq + lane + 32][0];
        const float* kr2 = &Ksh[qq + 64][0];
        const float* qr  = &Qsh[qq][0];
        float s0 = 0.f, s1 = 0.f, s2 = 0.f;
#pragma unroll
        for (int t = 0; t < 8; ++t) {
            float4 a  = *(const float4*)&qr[4 * t];
            float4 k0 = *(const float4*)&kr0[4 * t];
            float4 k1 = *(const float4*)&kr1[4 * t];
            float4 k2 = *(const float4*)&kr2[4 * t];
            s0 = fmaf(a.x, k0.x, fmaf(a.y, k0.y, fmaf(a.z, k0.z, fmaf(a.w, k0.w, s0))));
            s1 = fmaf(a.x, k1.x, fmaf(a.y, k1.y, fmaf(a.z, k1.z, fmaf(a.w, k1.w, s1))));
            s2 = fmaf(a.x, k2.x, fmaf(a.y, k2.y, fmaf(a.z, k2.z, fmaf(a.w, k2.w, s2))));
        }
        s0 *= scale; s1 *= scale; s2 *= scale;

        float m = fmaxf(fmaxf(s0, s1), s2);
#pragma unroll
        for (int o = 16; o; o >>= 1) m = fmaxf(m, __shfl_xor_sync(0xffffffffu, m, o));
        float e0 = __expf(s0 - m);
        float e1 = __expf(s1 - m);
        float e2 = __expf(s2 - m);
        float zz = e0 + e1 + ((lane == 0) ? e2 : 0.f);
#pragma unroll
        for (int o = 16; o; o >>= 1) zz += __shfl_xor_sync(0xffffffffu, zz, o);
        float rz = 1.0f / zz;
        float p0 = e0 * rz, p1 = e1 * rz, p2 = e2 * rz;

        int awo = (bh * SEQ + i) * WLEN;
        aw[awo + lane]      = p0;
        aw[awo + 32 + lane] = p1;
        if (lane == 0) aw[awo + 64] = p2;

        Psh[qq][lane]      = p0;
        Psh[qq][32 + lane] = p1;
        if (lane == 0) Psh[qq][64] = p2;
    }
    __syncwarp();

    const int p  = lane >> 3;
    const int d4 = (lane & 7) * 4;
    const float* base;
    int rstride;
    if (p == 0) { base = v + (size_t)(b * SEQ) * HDIM + colb + d4; rstride = HDIM; }
    else        { base = x + ((size_t)(b * SEQ) * 4 + p) * HDIM + colb + d4; rstride = 4 * HDIM; }

    const int ib = i0 + 4 * wq;
    const float* prow = &Psh[4 * wq][0];

    float4 acc[4];
#pragma unroll
    for (int j = 0; j < 4; ++j) acc[j] = make_float4(0.f, 0.f, 0.f, 0.f);

#define AGG_FMA(jj, ww, vv)                                             \
    {                                                                   \
        float pw = prow[(jj) * 72 + (ww) - (jj)];                       \
        acc[jj].x = fmaf(pw, (vv).x, acc[jj].x);                        \
        acc[jj].y = fmaf(pw, (vv).y, acc[jj].y);                        \
        acc[jj].z = fmaf(pw, (vv).z, acc[jj].z);                        \
        acc[jj].w = fmaf(pw, (vv).w, acc[jj].w);                        \
    }

    if (ib >= WIN && ib <= SEQ - 36) {
        const float* ptr = base + (size_t)(ib - WIN) * rstride;
        float4 vv[4];
#pragma unroll
        for (int t = 0; t < 4; ++t) { vv[t] = *(const float4*)ptr; ptr += rstride; }
#pragma unroll
        for (int w = 0; w < 4; ++w)
#pragma unroll
            for (int j = 0; j < 4; ++j)
                if (j <= w) AGG_FMA(j, w, vv[w]);
        for (int w0 = 4; w0 < 64; w0 += 4) {
#pragma unroll
            for (int t = 0; t < 4; ++t) { vv[t] = *(const float4*)ptr; ptr += rstride; }
#pragma unroll
            for (int t = 0; t < 4; ++t)
#pragma unroll
                for (int j = 0; j < 4; ++j)
                    AGG_FMA(j, w0 + t, vv[t]);
        }
#pragma unroll
        for (int t = 0; t < 4; ++t) { vv[t] = *(const float4*)ptr; ptr += rstride; }
#pragma unroll
        for (int w = 64; w < 68; ++w)
#pragma unroll
            for (int j = 0; j < 4; ++j)
                if (w - j < WLEN) AGG_FMA(j, w, vv[w - 64]);
    } else {
        for (int w = 0; w < 68; ++w) {
            int row = ib - WIN + w;
            if ((unsigned)row >= SEQ) continue;
            float4 vv = *(const float4*)(base + (size_t)row * rstride);
#pragma unroll
            for (int j = 0; j < 4; ++j) {
                int wj = w - j;
                if (wj >= 0 && wj < WLEN) AGG_FMA(j, w, vv);
            }
        }
    }
#undef AGG_FMA

#pragma unroll
    for (int j = 0; j < 4; ++j) {
        const int i = ib + j;
        if (p == 0)
            *(float4*)&xout[(size_t)(b * SEQ + i) * HDIM + colb + d4] = acc[j];
        else
            *(float4*)&vagg[((size_t)(b * SEQ + i) * 3 + (p - 1)) * HDIM + colb + d4] = acc[j];
    }
}

// ---------------- vec_dot + vec_norm + invariants (fused) ----------------
__global__ __launch_bounds__(256)
void reduce_inv_kernel(const float* __restrict__ vp, const float* __restrict__ x,
                       const float* __restrict__ ad, const float* __restrict__ an,
                       float* __restrict__ vd, float* __restrict__ vn,
                       float* __restrict__ inv)
{
    int idx = blockIdx.x * 256 + threadIdx.x;   // 4096*256
    int bn = idx >> 8, j = idx & 255;
    const float* r = vp + bn * 1536;
    float dot = r[j] * r[256 + j] + r[512 + j] * r[768 + j] + r[1024 + j] * r[1280 + j];
    const float* xr = x + (bn * 4 + 1) * 256 + j;
    float v0 = xr[0], v1 = xr[256], v2 = xr[512];
    float nrm = sqrtf(v0 * v0 + v1 * v1 + v2 * v2);
    vd[idx] = dot;
    vn[idx] = nrm;
    inv[bn * 512 + j]       = ad[0] * dot;
    inv[bn * 512 + 256 + j] = an[0] * nrm;
}

// ---------------- final epilogue ----------------
__global__ __launch_bounds__(256)
void final_kernel(const float* __restrict__ vd, const float* __restrict__ vn,
                  const float* __restrict__ o, const float* __restrict__ gate,
                  const float* __restrict__ vagg, const float* __restrict__ x,
                  float* __restrict__ out)
{
    int idx = blockIdx.x * 256 + threadIdx.x;   // 4096*256
    int bn = idx >> 8, j = idx & 255;
    const float* orow = o + bn * 768;
    float vdv = vd[idx], vnv = vn[idx];
    out[(bn * 4) * 256 + j] = vdv * orow[j] + vnv * orow[256 + j] + orow[512 + j];
    float g = gate[idx];
#pragma unroll
    for (int c = 0; c < 3; ++c) {
        int xoff = (bn * 4 + 1 + c) * 256 + j;
        out[xoff] = g * vagg[(bn * 3 + c) * 256 + j] + x[xoff];
    }
}

// ---------------- launch: two concurrent chains, fork/join via events ------
extern "C" void kernel_launch(void* const* d_in, const int* in_sizes, int n_in,
                              void* d_out, int out_size)
{
    const float* x    = (const float*)d_in[0];
    const float* Wq   = (const float*)d_in[1];
    const float* bq   = (const float*)d_in[2];
    const float* Wk   = (const float*)d_in[3];
    const float* bk   = (const float*)d_in[4];
    const float* Wv   = (const float*)d_in[5];
    const float* bv   = (const float*)d_in[6];
    const float* Wo   = (const float*)d_in[7];
    const float* bo   = (const float*)d_in[8];
    const float* Wvec = (const float*)d_in[9];
    const float* ad   = (const float*)d_in[10];
    const float* an   = (const float*)d_in[11];
    const float* Wg   = (const float*)d_in[12];
    const float* bg   = (const float*)d_in[13];

    float* S;
    cudaGetSymbolAddress((void**)&S, g_scratch);
    float* out = (float*)d_out;
    float* aw  = out + BATCH * SEQ * 4 * HDIM;

    const int M = BATCH * SEQ;   // 4096
    const int SMEM = 55296;

    // one-time host-side objects (created outside any graph capture; the
    // per-call launched work is identical on every invocation)
    static cudaStream_t sB = 0;
    static cudaEvent_t evF = 0, evB = 0;
    static int smem_set = 0;
    if (!sB) {
        cudaStreamCreateWithFlags(&sB, cudaStreamNonBlocking);
        cudaEventCreateWithFlags(&evF, cudaEventDisableTiming);
        cudaEventCreateWithFlags(&evB, cudaEventDisableTiming);
    }
    if (!smem_set) {
        cudaFuncSetAttribute(mma_gemm, cudaFuncAttributeMaxDynamicSharedMemorySize, SMEM);
        smem_set = 1;
    }

    // fork: chain B joins the (possibly capturing) origin stream
    cudaEventRecord(evF, 0);
    cudaStreamWaitEvent(sB, evF, 0);

    // ---- chain B (stream sB): vec_proj -> reduce_inv -> gate ----
    mma_gemm<<<dim3(8, 96, 1), 256, SMEM, sB>>>(x, Wvec, Wvec, Wvec,
                                                nullptr, nullptr, nullptr,
                                                S + OFF_VP, 0, 3 * M, 512, 256, 2, 0);
    reduce_inv_kernel<<<M, 256, 0, sB>>>(S + OFF_VP, x, ad, an,
                                         S + OFF_VD, S + OFF_VN, S + OFF_INV);
    mma_gemm<<<dim3(4, 32, 1), 256, SMEM, sB>>>(S + OFF_INV, Wg, Wg, Wg, bg, bg, bg,
                                                S + OFF_GATE, 0, M, 256, 512, 0, 1);
    cudaEventRecord(evB, sB);

    // ---- chain A (origin stream): QKV -> attn -> Wo ----
    mma_gemm<<<dim3(4, 32, 3), 256, SMEM>>>(x, Wq, Wk, Wv, bq, bk, bv,
                                            S + OFF_Q, 1048576, M, 256, 256, 1, 0);
    attn_kernel<<<dim3(SEQ / 32, 16), 256>>>(S + OFF_Q, S + OFF_K, S + OFF_V, x, aw,
                                             S + OFF_XOUT, S + OFF_VAGG);
    mma_gemm<<<dim3(12, 32, 1), 256, SMEM>>>(S + OFF_XOUT, Wo, Wo, Wo, bo, bo, bo,
                                             S + OFF_O, 0, M, 768, 256, 0, 0);

    // join and finish
    cudaStreamWaitEvent(0, evB, 0);
    final_kernel<<<M, 256>>>(S + OFF_VD, S + OFF_VN, S + OFF_O, S + OFF_GATE,
                             S + OFF_VAGG, x, out);
}

// round 17
// speedup vs baseline: 3.8389x; 1.0301x over previous
#include <cuda_runtime.h>
#include <math.h>

#define BATCH 2
#define SEQ   2048
#define HDIM  256
#define NHEAD 8
#define HD    32
#define WIN   32
#define WLEN  65

// ---------------- scratch (static __device__, no allocation) ----------------
#define OFF_Q     0
#define OFF_K     1048576
#define OFF_V     2097152
#define OFF_VP    3145728      // vec_proj 12288x512
#define OFF_VD    9437184      // vec_dot 4096x256
#define OFF_VN    10485760     // vec_norm 4096x256
#define OFF_INV   11534336     // invariants 4096x512
#define OFF_XOUT  13631488     // 4096x256
#define OFF_VAGG  14680064     // 4096x3x256
#define OFF_O     17825792     // 4096x768
#define OFF_GATE  20971520     // 4096x256
#define SCRATCH_FLOATS 22020096

__device__ float g_scratch[SCRATCH_FLOATS];

// round-to-nearest fp32 -> tf32
__device__ __forceinline__ float tf32r(float x) {
    unsigned u;
    asm("cvt.rna.tf32.f32 %0, %1;" : "=r"(u) : "f"(x));
    return __uint_as_float(u);
}
__device__ __forceinline__ float4 tf32r4(float4 v) {
    return make_float4(tf32r(v.x), tf32r(v.y), tf32r(v.z), tf32r(v.w));
}

#define MMA_TF32(acc, a, b)                                                  \
    asm volatile(                                                            \
        "mma.sync.aligned.m16n8k8.row.col.f32.tf32.tf32.f32 "                \
        "{%0,%1,%2,%3}, {%4,%5,%6,%7}, {%8,%9}, {%0,%1,%2,%3};"              \
        : "+f"((acc)[0]), "+f"((acc)[1]), "+f"((acc)[2]), "+f"((acc)[3])     \
        : "r"((a)[0]), "r"((a)[1]), "r"((a)[2]), "r"((a)[3]),                \
          "r"((b)[0]), "r"((b)[1]))

// ---------------- TF32 tensor-core GEMM, 2-stage smem double buffer --------
#define AS(s, m, kk) dsm[(s) * 4608 + (m) * 36 + (kk)]
#define BS(s, kk, n) dsm[9216 + (s) * 2304 + (kk) * 72 + (n)]

__global__ __launch_bounds__(256)
void mma_gemm(const float* __restrict__ A,
              const float* __restrict__ B0, const float* __restrict__ B1,
              const float* __restrict__ B2,
              const float* __restrict__ c0, const float* __restrict__ c1,
              const float* __restrict__ c2,
              float* __restrict__ C, int Cstride,
              int M, int Nout, int K, int amode, int act)
{
    extern __shared__ __align__(16) float dsm[];

    const int z = blockIdx.z;
    const float* Bm   = (z == 0) ? B0 : (z == 1) ? B1 : B2;
    const float* bias = (z == 0) ? c0 : (z == 1) ? c1 : c2;
    C += (size_t)z * Cstride;

    const int tid  = threadIdx.x;
    const int lane = tid & 31;
    const int warp = tid >> 5;
    const int g    = lane >> 2;
    const int tig  = lane & 3;
    const int wm   = (warp & 3) * 32;
    const int wn   = (warp >> 2) * 32;
    const int m0   = blockIdx.y * 128;
    const int n0   = blockIdx.x * 64;

    const int rA = tid >> 1;
    const int kc = (tid & 1) * 16;
    const int rowA = m0 + rA;
    int aoff;
    if (amode == 1)      aoff = rowA * 1024;
    else if (amode == 2) { int t = rowA / 3; int c = rowA - 3 * t; aoff = (4 * t + 1 + c) * 256; }
    else                 aoff = rowA * K;

    const int kB = tid >> 3;
    const int nB = (tid & 7) * 8;

    float4 pa[4];
    float4 pb[2];
    {
        const float* ap = A + aoff + kc;
#pragma unroll
        for (int j = 0; j < 4; ++j) pa[j] = *(const float4*)(ap + j * 4);
        const float* bp = Bm + kB * Nout + n0 + nB;
        pb[0] = *(const float4*)bp;
        pb[1] = *(const float4*)(bp + 4);
    }
#pragma unroll
    for (int j = 0; j < 4; ++j)
        *(float4*)&AS(0, rA, kc + j * 4) = tf32r4(pa[j]);
    *(float4*)&BS(0, kB, nB)     = tf32r4(pb[0]);
    *(float4*)&BS(0, kB, nB + 4) = tf32r4(pb[1]);

    float acc[2][4][4];
#pragma unroll
    for (int mt = 0; mt < 2; ++mt)
#pragma unroll
        for (int nt = 0; nt < 4; ++nt)
#pragma unroll
            for (int r = 0; r < 4; ++r) acc[mt][nt][r] = 0.f;

    const int NT = K >> 5;
    int st = 0;
    for (int kt = 0; kt < NT; ++kt) {
        __syncthreads();
        const bool more = (kt + 1 < NT);
        if (more) {
            const int k1 = (kt + 1) << 5;
            const float* ap = A + aoff + k1 + kc;
#pragma unroll
            for (int j = 0; j < 4; ++j) pa[j] = *(const float4*)(ap + j * 4);
            const float* bp = Bm + (k1 + kB) * Nout + n0 + nB;
            pb[0] = *(const float4*)bp;
            pb[1] = *(const float4*)(bp + 4);
        }

#pragma unroll
        for (int kq = 0; kq < 4; ++kq) {
            const int kk = kq * 8;
            unsigned a[2][4], b[4][2];
#pragma unroll
            for (int mt = 0; mt < 2; ++mt) {
                const int mr = wm + mt * 16 + g;
                a[mt][0] = __float_as_uint(AS(st, mr, kk + tig));
                a[mt][1] = __float_as_uint(AS(st, mr + 8, kk + tig));
                a[mt][2] = __float_as_uint(AS(st, mr, kk + tig + 4));
                a[mt][3] = __float_as_uint(AS(st, mr + 8, kk + tig + 4));
            }
#pragma unroll
            for (int nt = 0; nt < 4; ++nt) {
                const int nc = wn + nt * 8 + g;
                b[nt][0] = __float_as_uint(BS(st, kk + tig, nc));
                b[nt][1] = __float_as_uint(BS(st, kk + tig + 4, nc));
            }
#pragma unroll
            for (int mt = 0; mt < 2; ++mt)
#pragma unroll
                for (int nt = 0; nt < 4; ++nt)
                    MMA_TF32(acc[mt][nt], a[mt], b[nt]);
        }

        if (more) {
            const int s2 = st ^ 1;
#pragma unroll
            for (int j = 0; j < 4; ++j)
                *(float4*)&AS(s2, rA, kc + j * 4) = tf32r4(pa[j]);
            *(float4*)&BS(s2, kB, nB)     = tf32r4(pb[0]);
            *(float4*)&BS(s2, kB, nB + 4) = tf32r4(pb[1]);
        }
        st ^= 1;
    }

#pragma unroll
    for (int mt = 0; mt < 2; ++mt) {
        const int row = m0 + wm + mt * 16 + g;
#pragma unroll
        for (int nt = 0; nt < 4; ++nt) {
            const int col = n0 + wn + nt * 8 + 2 * tig;
            float b0 = 0.f, b1 = 0.f;
            if (bias) { b0 = bias[col]; b1 = bias[col + 1]; }
            float2 r0 = make_float2(acc[mt][nt][0] + b0, acc[mt][nt][1] + b1);
            float2 r1 = make_float2(acc[mt][nt][2] + b0, acc[mt][nt][3] + b1);
            if (act == 1) {
                r0.x = 1.f / (1.f + __expf(-r0.x));
                r0.y = 1.f / (1.f + __expf(-r0.y));
                r1.x = 1.f / (1.f + __expf(-r1.x));
                r1.y = 1.f / (1.f + __expf(-r1.y));
            }
            *(float2*)&C[row * Nout + col] = r0;
            *(float2*)&C[(row + 8) * Nout + col] = r1;
        }
    }
}

// ---------------- windowed attention via TF32 MMA --------------------------
// Block = 32 queries of one (b,h). Dynamic smem:
//   W  [96][164] : K(d 0..31) | V(32..63) | X(64..159), window rows zero-padded
//   Qs [32][36]
//   P  [32][100] : scores, then band probabilities (zero-filled outside band)
// Phase 1: S(32x96) = Q @ Kwin^T   (6 warps x 16 cols, m16n8k8)
// Phase 2: fp32 softmax per query (banded; padded-zero scores included)
// Phase 3: Out(32x128) = P @ [V|X]win  (8 warps x 16 cols)
#define SW_W   0
#define SW_Q   15744
#define SW_P   16896
#define ATTN_SMEM ((16896 + 3200) * 4)

__global__ __launch_bounds__(256)
void attn_kernel(const float* __restrict__ q, const float* __restrict__ k,
                 const float* __restrict__ v, const float* __restrict__ x,
                 float* __restrict__ aw, float* __restrict__ xout,
                 float* __restrict__ vagg)
{
    extern __shared__ __align__(16) float sm[];
    float* W  = sm + SW_W;    // stride 164
    float* Qs = sm + SW_Q;    // stride 36
    float* P  = sm + SW_P;    // stride 100

    const float scale = 0.17677669529663687f; // 1/sqrt(32)
    const int tid  = threadIdx.x;
    const int lane = tid & 31;
    const int warp = tid >> 5;
    const int g    = lane >> 2;
    const int tig  = lane & 3;
    const int i0   = blockIdx.x * 32;
    const int bh   = blockIdx.y;
    const int b    = bh >> 3;
    const int hh   = bh & 7;
    const int colb = hh * HD;

    // ---- stage window rows [i0-32, i0+63]: 96 rows x 40 float4 ----
    for (int e = tid; e < 96 * 40; e += 256) {
        int r = e / 40, c = e - 40 * r;
        int seq = i0 + r - WIN;
        float4 val = make_float4(0.f, 0.f, 0.f, 0.f);
        if ((unsigned)seq < SEQ) {
            if (c < 8)
                val = *(const float4*)&k[(size_t)(b * SEQ + seq) * HDIM + colb + 4 * c];
            else if (c < 16)
                val = *(const float4*)&v[(size_t)(b * SEQ + seq) * HDIM + colb + 4 * (c - 8)];
            else {
                int cc = c - 16;
                val = *(const float4*)&x[((size_t)(b * SEQ + seq) * 4 + 1 + (cc >> 3)) * HDIM
                                         + colb + 4 * (cc & 7)];
            }
        }
        *(float4*)&W[r * 164 + 4 * c] = tf32r4(val);
    }
    {   // stage Q (32 rows x 8 float4 = 256 threads)
        int q8 = tid >> 3, j = tid & 7;
        *(float4*)&Qs[q8 * 36 + 4 * j] =
            tf32r4(*(const float4*)&q[(size_t)(b * SEQ + i0 + q8) * HDIM + colb + 4 * j]);
    }
    __syncthreads();

    // ---- phase 1: scores (warps 0..5, each 16 of 96 window cols) ----
    if (warp < 6) {
        float acc[2][2][4];
#pragma unroll
        for (int mt = 0; mt < 2; ++mt)
#pragma unroll
            for (int nt = 0; nt < 2; ++nt)
#pragma unroll
                for (int r = 0; r < 4; ++r) acc[mt][nt][r] = 0.f;
#pragma unroll
        for (int kq = 0; kq < 4; ++kq) {
            const int kk = kq * 8;
            unsigned a[2][4], bb[2][2];
#pragma unroll
            for (int mt = 0; mt < 2; ++mt) {
                const int mr = 16 * mt + g;
                a[mt][0] = __float_as_uint(Qs[mr * 36 + kk + tig]);
                a[mt][1] = __float_as_uint(Qs[(mr + 8) * 36 + kk + tig]);
                a[mt][2] = __float_as_uint(Qs[mr * 36 + kk + tig + 4]);
                a[mt][3] = __float_as_uint(Qs[(mr + 8) * 36 + kk + tig + 4]);
            }
#pragma unroll
            for (int nt = 0; nt < 2; ++nt) {
                const int rn = 16 * warp + 8 * nt + g;   // window row (transposed read)
                bb[nt][0] = __float_as_uint(W[rn * 164 + kk + tig]);
                bb[nt][1] = __float_as_uint(W[rn * 164 + kk + tig + 4]);
            }
#pragma unroll
            for (int mt = 0; mt < 2; ++mt)
#pragma unroll
                for (int nt = 0; nt < 2; ++nt)
                    MMA_TF32(acc[mt][nt], a[mt], bb[nt]);
        }
        // write raw scores into P buffer
#pragma unroll
        for (int mt = 0; mt < 2; ++mt) {
            const int row = 16 * mt + g;
#pragma unroll
            for (int nt = 0; nt < 2; ++nt) {
                const int col = 16 * warp + 8 * nt + 2 * tig;
                P[row * 100 + col]           = acc[mt][nt][0];
                P[row * 100 + col + 1]       = acc[mt][nt][1];
                P[(row + 8) * 100 + col]     = acc[mt][nt][2];
                P[(row + 8) * 100 + col + 1] = acc[mt][nt][3];
            }
        }
    }
    __syncthreads();

    // ---- phase 2: fp32 softmax, 4 queries per warp ----
#pragma unroll
    for (int j = 0; j < 4; ++j) {
        const int qq = 4 * warp + j;
        const int i  = i0 + qq;
        float s0 = P[qq * 100 + qq + lane] * scale;
        float s1 = P[qq * 100 + qq + 32 + lane] * scale;
        float s2 = P[qq * 100 + qq + 64] * scale;     // broadcast
        __syncwarp();
        // zero the whole row (band re-filled below)
        P[qq * 100 + lane]      = 0.f;
        P[qq * 100 + 32 + lane] = 0.f;
        P[qq * 100 + 64 + lane] = 0.f;
        if (lane < 4) P[qq * 100 + 96 + lane] = 0.f;

        float m = fmaxf(fmaxf(s0, s1), s2);
#pragma unroll
        for (int o = 16; o; o >>= 1) m = fmaxf(m, __shfl_xor_sync(0xffffffffu, m, o));
        float e0 = __expf(s0 - m);
        float e1 = __expf(s1 - m);
        float e2 = __expf(s2 - m);
        float zz = e0 + e1 + ((lane == 0) ? e2 : 0.f);
#pragma unroll
        for (int o = 16; o; o >>= 1) zz += __shfl_xor_sync(0xffffffffu, zz, o);
        float rz = 1.0f / zz;
        float p0 = e0 * rz, p1 = e1 * rz, p2 = e2 * rz;

        int awo = (bh * SEQ + i) * WLEN;
        aw[awo + lane]      = p0;
        aw[awo + 32 + lane] = p1;
        if (lane == 0) aw[awo + 64] = p2;

        __syncwarp();
        P[qq * 100 + qq + lane]      = tf32r(p0);
        P[qq * 100 + qq + 32 + lane] = tf32r(p1);
        if (lane == 0) P[qq * 100 + qq + 64] = tf32r(p2);
    }
    __syncthreads();

    // ---- phase 3: Out = P @ [V|X]win  (8 warps x 16 of 128 d-cols) ----
    float acc[2][2][4];
#pragma unroll
    for (int mt = 0; mt < 2; ++mt)
#pragma unroll
        for (int nt = 0; nt < 2; ++nt)
#pragma unroll
            for (int r = 0; r < 4; ++r) acc[mt][nt][r] = 0.f;

#pragma unroll
    for (int kq = 0; kq < 12; ++kq) {
        const int kk = kq * 8;                        // window-row chunk
        unsigned a[2][4], bb[2][2];
#pragma unroll
        for (int mt = 0; mt < 2; ++mt) {
            const int mr = 16 * mt + g;
            a[mt][0] = __float_as_uint(P[mr * 100 + kk + tig]);
            a[mt][1] = __float_as_uint(P[(mr + 8) * 100 + kk + tig]);
            a[mt][2] = __float_as_uint(P[mr * 100 + kk + tig + 4]);
            a[mt][3] = __float_as_uint(P[(mr + 8) * 100 + kk + tig + 4]);
        }
#pragma unroll
        for (int nt = 0; nt < 2; ++nt) {
            const int nc = 32 + 16 * warp + 8 * nt + g;   // W col (V|X area)
            bb[nt][0] = __float_as_uint(W[(kk + tig) * 164 + nc]);
            bb[nt][1] = __float_as_uint(W[(kk + tig + 4) * 164 + nc]);
        }
#pragma unroll
        for (int mt = 0; mt < 2; ++mt)
#pragma unroll
            for (int nt = 0; nt < 2; ++nt)
                MMA_TF32(acc[mt][nt], a[mt], bb[nt]);
    }

    // ---- epilogue: rows i0+16mt+g(+8), cols n=16*warp+8nt+2tig(+1) ----
#pragma unroll
    for (int mt = 0; mt < 2; ++mt) {
#pragma unroll
        for (int nt = 0; nt < 2; ++nt) {
            const int n = 16 * warp + 8 * nt + 2 * tig;
            float2 r0 = make_float2(acc[mt][nt][0], acc[mt][nt][1]);
            float2 r1 = make_float2(acc[mt][nt][2], acc[mt][nt][3]);
            const int row0 = i0 + 16 * mt + g;
            if (n < 32) {
                *(float2*)&xout[(size_t)(b * SEQ + row0) * HDIM + colb + n] = r0;
                *(float2*)&xout[(size_t)(b * SEQ + row0 + 8) * HDIM + colb + n] = r1;
            } else {
                const int pl = (n - 32) >> 5, d = (n - 32) & 31;
                *(float2*)&vagg[((size_t)(b * SEQ + row0) * 3 + pl) * HDIM + colb + d] = r0;
                *(float2*)&vagg[((size_t)(b * SEQ + row0 + 8) * 3 + pl) * HDIM + colb + d] = r1;
            }
        }
    }
}

// ---------------- vec_dot + vec_norm + invariants (fused) ----------------
__global__ __launch_bounds__(256)
void reduce_inv_kernel(const float* __restrict__ vp, const float* __restrict__ x,
                       const float* __restrict__ ad, const float* __restrict__ an,
                       float* __restrict__ vd, float* __restrict__ vn,
                       float* __restrict__ inv)
{
    int idx = blockIdx.x * 256 + threadIdx.x;   // 4096*256
    int bn = idx >> 8, j = idx & 255;
    const float* r = vp + bn * 1536;
    float dot = r[j] * r[256 + j] + r[512 + j] * r[768 + j] + r[1024 + j] * r[1280 + j];
    const float* xr = x + (bn * 4 + 1) * 256 + j;
    float v0 = xr[0], v1 = xr[256], v2 = xr[512];
    float nrm = sqrtf(v0 * v0 + v1 * v1 + v2 * v2);
    vd[idx] = dot;
    vn[idx] = nrm;
    inv[bn * 512 + j]       = ad[0] * dot;
    inv[bn * 512 + 256 + j] = an[0] * nrm;
}

// ---------------- final epilogue ----------------
__global__ __launch_bounds__(256)
void final_kernel(const float* __restrict__ vd, const float* __restrict__ vn,
                  const float* __restrict__ o, const float* __restrict__ gate,
                  const float* __restrict__ vagg, const float* __restrict__ x,
                  float* __restrict__ out)
{
    int idx = blockIdx.x * 256 + threadIdx.x;   // 4096*256
    int bn = idx >> 8, j = idx & 255;
    const float* orow = o + bn * 768;
    float vdv = vd[idx], vnv = vn[idx];
    out[(bn * 4) * 256 + j] = vdv * orow[j] + vnv * orow[256 + j] + orow[512 + j];
    float g = gate[idx];
#pragma unroll
    for (int c = 0; c < 3; ++c) {
        int xoff = (bn * 4 + 1 + c) * 256 + j;
        out[xoff] = g * vagg[(bn * 3 + c) * 256 + j] + x[xoff];
    }
}

// ---------------- launch: two concurrent chains, fork/join via events ------
extern "C" void kernel_launch(void* const* d_in, const int* in_sizes, int n_in,
                              void* d_out, int out_size)
{
    const float* x    = (const float*)d_in[0];
    const float* Wq   = (const float*)d_in[1];
    const float* bq   = (const float*)d_in[2];
    const float* Wk   = (const float*)d_in[3];
    const float* bk   = (const float*)d_in[4];
    const float* Wv   = (const float*)d_in[5];
    const float* bv   = (const float*)d_in[6];
    const float* Wo   = (const float*)d_in[7];
    const float* bo   = (const float*)d_in[8];
    const float* Wvec = (const float*)d_in[9];
    const float* ad   = (const float*)d_in[10];
    const float* an   = (const float*)d_in[11];
    const float* Wg   = (const float*)d_in[12];
    const float* bg   = (const float*)d_in[13];

    float* S;
    cudaGetSymbolAddress((void**)&S, g_scratch);
    float* out = (float*)d_out;
    float* aw  = out + BATCH * SEQ * 4 * HDIM;

    const int M = BATCH * SEQ;   // 4096
    const int SMEM = 55296;

    static cudaStream_t sB = 0;
    static cudaEvent_t evF = 0, evB = 0;
    static int attr_set = 0;
    if (!sB) {
        cudaStreamCreateWithFlags(&sB, cudaStreamNonBlocking);
        cudaEventCreateWithFlags(&evF, cudaEventDisableTiming);
        cudaEventCreateWithFlags(&evB, cudaEventDisableTiming);
    }
    if (!attr_set) {
        cudaFuncSetAttribute(mma_gemm, cudaFuncAttributeMaxDynamicSharedMemorySize, SMEM);
        cudaFuncSetAttribute(attn_kernel, cudaFuncAttributeMaxDynamicSharedMemorySize, ATTN_SMEM);
        attr_set = 1;
    }

    // fork
    cudaEventRecord(evF, 0);
    cudaStreamWaitEvent(sB, evF, 0);

    // ---- chain B (stream sB): vec_proj -> reduce_inv -> gate ----
    mma_gemm<<<dim3(8, 96, 1), 256, SMEM, sB>>>(x, Wvec, Wvec, Wvec,
                                                nullptr, nullptr, nullptr,
                                                S + OFF_VP, 0, 3 * M, 512, 256, 2, 0);
    reduce_inv_kernel<<<M, 256, 0, sB>>>(S + OFF_VP, x, ad, an,
                                         S + OFF_VD, S + OFF_VN, S + OFF_INV);
    mma_gemm<<<dim3(4, 32, 1), 256, SMEM, sB>>>(S + OFF_INV, Wg, Wg, Wg, bg, bg, bg,
                                                S + OFF_GATE, 0, M, 256, 512, 0, 1);
    cudaEventRecord(evB, sB);

    // ---- chain A (origin stream): QKV -> attn -> Wo ----
    mma_gemm<<<dim3(4, 32, 3), 256, SMEM>>>(x, Wq, Wk, Wv, bq, bk, bv,
                                            S + OFF_Q, 1048576, M, 256, 256, 1, 0);
    attn_kernel<<<dim3(SEQ / 32, 16), 256, ATTN_SMEM>>>(S + OFF_Q, S + OFF_K, S + OFF_V,
                                                        x, aw, S + OFF_XOUT, S + OFF_VAGG);
    mma_gemm<<<dim3(12, 32, 1), 256, SMEM>>>(S + OFF_XOUT, Wo, Wo, Wo, bo, bo, bo,
                                             S + OFF_O, 0, M, 768, 256, 0, 0);

    // join and finish
    cudaStreamWaitEvent(0, evB, 0);
    final_kernel<<<M, 256>>>(S + OFF_VD, S + OFF_VN, S + OFF_O, S + OFF_GATE,
                             S + OFF_VAGG, x, out);
}